// round 11
// baseline (speedup 1.0000x reference)
#include <cuda_runtime.h>
#include <cuda_bf16.h>
#include <cuda_fp16.h>
#include <math.h>
#include <stdint.h>

#define N_NODES 20000
#define N_EDGES 320000
#define FDIM 32
#define HDIM 128
#define NHEADS 4
#define KVDIM 1024    // fused keff|v row (fp16)

// ---------------- device-global scratch ----------------
__device__ float g_h[N_NODES * HDIM];
__device__ __half g_kvh[N_NODES * KVDIM];
__device__ float g_xr[N_NODES * HDIM];
__device__ float g_wb[N_NODES * NHEADS];
__device__ int   g_indptr[N_NODES + 1];
__device__ int   g_cnt[N_NODES];
__device__ int   g_cursor[N_NODES];
__device__ int   g_csrc[N_EDGES];
// fp16 activation buffers
__device__ __half g_ah[N_NODES * HDIM];    // hn (LN output)
__device__ __half g_mh[N_NODES * 512];     // FFN mid
__device__ __half g_xh[N_NODES * 64];      // padded input
// G = scale * Wq Wk^T per head (B-layout [n=h*128+i][k=j]) + bvec
__device__ float g_G[2 * 512 * 128];
__device__ float g_bvec[2 * 4 * 128];
// packed transposed fp16 weights
#define WL_KEFF 0
#define WL_V    65536
#define WL_SKIP 131072
#define WL_W1   147456
#define WL_W2   212992
#define W_PER_LAYER 278528
#define W_WIN_OFF 557056
#define W_TOTAL 565248
#define KVS_N 1152
#define PREP_TOTAL (W_TOTAL + 2 * KVS_N + N_NODES * 64)
__device__ __half g_wh[W_TOTAL];
__device__ float g_bkvs[2 * KVS_N];

// ---------------- helpers ----------------
__device__ __forceinline__ uint32_t smem_to_u32(const void* p) {
    uint32_t a;
    asm("{ .reg .u64 t; cvta.to.shared.u64 t, %1; cvt.u32.u64 %0, t; }"
        : "=r"(a) : "l"(p));
    return a;
}
#define SWZ128(bo) ((bo) ^ (((bo) >> 3) & 0x70))

__device__ __forceinline__ void cp_async16(uint32_t dst, const void* src, int szbytes) {
    asm volatile("cp.async.cg.shared.global [%0], [%1], 16, %2;"
        :: "r"(dst), "l"(src), "r"(szbytes));
}
#define CP_COMMIT() asm volatile("cp.async.commit_group;" ::: "memory")
#define CP_WAIT1()  asm volatile("cp.async.wait_group 1;" ::: "memory")

__device__ __forceinline__ void ldsm_x4(uint32_t* r, uint32_t addr) {
    asm volatile("ldmatrix.sync.aligned.m8n8.x4.shared.b16 {%0,%1,%2,%3}, [%4];"
        : "=r"(r[0]), "=r"(r[1]), "=r"(r[2]), "=r"(r[3]) : "r"(addr));
}
__device__ __forceinline__ void mma16816h(float* c, const uint32_t* a, const uint32_t* b) {
    asm volatile("mma.sync.aligned.m16n8k16.row.col.f32.f16.f16.f32 "
        "{%0,%1,%2,%3}, {%4,%5,%6,%7}, {%8,%9}, {%0,%1,%2,%3};"
        : "+f"(c[0]), "+f"(c[1]), "+f"(c[2]), "+f"(c[3])
        : "r"(a[0]), "r"(a[1]), "r"(a[2]), "r"(a[3]), "r"(b[0]), "r"(b[1]));
}
__device__ __forceinline__ float gelu_f(float x) {
    return 0.5f * x * (1.0f + erff(x * 0.70710678118654752f));
}
__device__ __forceinline__ float4 h4_to_f4(uint2 raw) {
    const __half2 h0 = *reinterpret_cast<__half2*>(&raw.x);
    const __half2 h1 = *reinterpret_cast<__half2*>(&raw.y);
    const float2 a = __half22float2(h0);
    const float2 b = __half22float2(h1);
    return make_float4(a.x, a.y, b.x, b.y);
}

// ---------------- G precompute: G_h = scale*Wq_h Wk_h^T, bvec ----------------
__global__ void gmat_kernel(const float* __restrict__ Wq,
                            const float* __restrict__ Wk,
                            const float* __restrict__ bq)
{
    const float scale = 0.08838834764831845f;
    int idx = blockIdx.x * blockDim.x + threadIdx.x;
    if (idx < 131072) {
        const int l = idx >> 16, r = idx & 65535;
        const int n = r >> 7, k = r & 127;
        const int hh = n >> 7, i = n & 127;
        const float4* wq = (const float4*)(Wq + l * 65536 + i * 512 + hh * 128);
        const float4* wk = (const float4*)(Wk + l * 65536 + k * 512 + hh * 128);
        float s = 0.f;
        #pragma unroll 8
        for (int a = 0; a < 32; a++) {
            const float4 qa = __ldg(&wq[a]);
            const float4 ka = __ldg(&wk[a]);
            s += qa.x * ka.x + qa.y * ka.y + qa.z * ka.z + qa.w * ka.w;
        }
        g_G[idx] = s * scale;
    } else if (idx < 131072 + 1024) {
        const int r = idx - 131072;
        const int l = r >> 9, r2 = r & 511;
        const int hh = r2 >> 7, j = r2 & 127;
        const float* b = bq + l * 512 + hh * 128;
        const float* wk = Wk + l * 65536 + j * 512 + hh * 128;
        float s = 0.f;
        for (int a = 0; a < 128; a++) s += __ldg(&b[a]) * __ldg(&wk[a]);
        g_bvec[r] = s * scale;
    }
}

// ---------------- one-shot packer: fp16 weights + biases + x ----------------
__global__ void prep_all(
    const float* __restrict__ Wv, const float* __restrict__ Wskip,
    const float* __restrict__ W1, const float* __restrict__ W2,
    const float* __restrict__ Win,
    const float* __restrict__ bv, const float* __restrict__ bskip,
    const float* __restrict__ x)
{
    int idx = blockIdx.x * blockDim.x + threadIdx.x;
    if (idx >= PREP_TOTAL) return;
    if (idx >= W_TOTAL + 2 * KVS_N) {
        const int r = idx - (W_TOTAL + 2 * KVS_N);
        const int row = r >> 6, k = r & 63;
        const float val = (k < 32) ? __ldg(&x[row * 32 + k]) : 0.f;
        g_xh[r] = __float2half_rn(val);
        return;
    }
    if (idx >= W_TOTAL) {
        const int r = idx - W_TOTAL;
        const int l = r / KVS_N, c = r % KVS_N;
        g_bkvs[r] = (c < 512)  ? 0.f
                  : (c < 1024) ? __ldg(&bv[l * 512 + c - 512])
                               : __ldg(&bskip[l * 128 + c - 1024]);
        return;
    }
    float val;
    if (idx < W_WIN_OFF) {
        const int l = idx / W_PER_LAYER, r = idx % W_PER_LAYER;
        if (r < WL_V) {
            val = g_G[l * 65536 + r];
        } else if (r < WL_SKIP) {
            const int r2 = r - WL_V, n = r2 / 128, k = r2 % 128;
            val = __ldg(&Wv[l * 65536 + k * 512 + n]);
        } else if (r < WL_W1) {
            const int r3 = r - WL_SKIP, n = r3 / 128, k = r3 % 128;
            val = __ldg(&Wskip[l * 16384 + k * 128 + n]);
        } else if (r < WL_W2) {
            const int r4 = r - WL_W1, n = r4 / 128, k = r4 % 128;
            val = __ldg(&W1[l * 65536 + k * 512 + n]);
        } else {
            const int r5 = r - WL_W2, n = r5 / 512, k = r5 % 512;
            val = __ldg(&W2[l * 65536 + k * 128 + n]);
        }
    } else {
        const int r6 = idx - W_WIN_OFF, n = r6 / 64, k = r6 % 64;
        val = (k < 32) ? __ldg(&Win[k * 128 + n]) : 0.f;
    }
    g_wh[idx] = __float2half_rn(val);
}

// ---------------- CSR build ----------------
__global__ void zero_cnt_kernel() {
    int i = blockIdx.x * blockDim.x + threadIdx.x;
    if (i < N_NODES) g_cnt[i] = 0;
}
__global__ void deg_kernel(const int* __restrict__ ei) {
    int e = blockIdx.x * blockDim.x + threadIdx.x;
    if (e < N_EDGES) atomicAdd(&g_cnt[ei[N_EDGES + e]], 1);
}
__global__ void scan_kernel() {
    __shared__ int wsum[32];
    __shared__ int carry;
    const int tid = threadIdx.x, lane = tid & 31, wid = tid >> 5;
    if (tid == 0) { carry = 0; g_indptr[0] = 0; }
    __syncthreads();
    for (int base = 0; base < N_NODES; base += 1024) {
        int i = base + tid;
        int v = (i < N_NODES) ? g_cnt[i] : 0;
        int x = v;
        #pragma unroll
        for (int off = 1; off < 32; off <<= 1) {
            int y = __shfl_up_sync(0xffffffffu, x, off);
            if (lane >= off) x += y;
        }
        if (lane == 31) wsum[wid] = x;
        __syncthreads();
        if (wid == 0) {
            int w = wsum[lane];
            #pragma unroll
            for (int off = 1; off < 32; off <<= 1) {
                int y = __shfl_up_sync(0xffffffffu, w, off);
                if (lane >= off) w += y;
            }
            wsum[lane] = w;
        }
        __syncthreads();
        int incl = carry + (wid > 0 ? wsum[wid - 1] : 0) + x;
        if (i < N_NODES) {
            g_indptr[i + 1] = incl;
            g_cursor[i] = incl - v;
        }
        __syncthreads();
        if (tid == 1023) carry = incl;
        __syncthreads();
    }
}
__global__ void scatter_kernel(const int* __restrict__ ei) {
    int e = blockIdx.x * blockDim.x + threadIdx.x;
    if (e < N_EDGES) {
        int s = ei[e];
        int d = ei[N_EDGES + e];
        int pos = atomicAdd(&g_cursor[d], 1);
        g_csrc[pos] = s;
    }
}

// ---------------- wb: per-node bias term hn_s . bvec_h ----------------
__global__ void wb_kernel(const float* __restrict__ bvec) {
    int t = blockIdx.x * blockDim.x + threadIdx.x;
    if (t >= N_NODES * NHEADS) return;
    const int node = t >> 2, hh = t & 3;
    const float* bv = bvec + hh * 128;
    float s = 0.f;
    #pragma unroll 8
    for (int j = 0; j < 32; j++) {
        const float4 a = h4_to_f4(*(const uint2*)(g_ah + (size_t)node * 128 + j * 4));
        const float4 w = *(const float4*)(bv + j * 4);
        s += a.x * w.x + a.y * w.y + a.z * w.z + a.w * w.w;
    }
    g_wb[t] = s;
}

// ---------------- fp16 HMMA GEMM: CTA 256x128, warp tile 64x64 ----------------
// 256 threads, 8 warps (4 row-groups x 2 col-groups). K-chunk 64.
// SMEM: stage = A 32KB + B 16KB; 2 stages = 96KB; LN epilogues reuse as
// Cs 256x132 f32 (135KB alloc for EPI 2/3 only).
// EPI 1: OutH = fp16(gelu(acc + bias)), direct fragment stores (pitch N)
// EPI 2: C += gs*(acc + bias); LN(C) -> OutF(fp32) or OutH(fp16)  (N==128)
// EPI 3: C  = acc + bias;      LN(C) -> OutH(fp16)                (N==128)
// EPI 4: col0<1024 -> fp16 kv (pitch 1024); col0>=1024 -> fp32 xr (pitch 128)
#define MG_SMEM_PIPE  98304
#define MG_SMEM_LN    (256 * 132 * 4)

template <int EPI>
__global__ void __launch_bounds__(256) mma_gemm_kernel(
    const __half* __restrict__ A, const __half* __restrict__ Bt,
    const float* __restrict__ bias, float* __restrict__ C,
    const float* __restrict__ gscale,
    __half* __restrict__ OutH, float* __restrict__ OutF,
    const float* __restrict__ lns, const float* __restrict__ lnb,
    float* __restrict__ OutXr,
    int M, int N, int K)
{
    extern __shared__ char smem[];
    float* Cs = (float*)smem;
    const int tid = threadIdx.x;
    const int wid = tid >> 5, lane = tid & 31;
    const int wr = wid & 3, wc = wid >> 2;       // 4 row-groups x 2 col-groups
    const int row0 = blockIdx.y * 256, col0 = blockIdx.x * 128;
    const uint32_t sb = smem_to_u32(smem);

    float acc[4][8][4];
    #pragma unroll
    for (int a = 0; a < 4; a++)
        #pragma unroll
        for (int b = 0; b < 8; b++)
            #pragma unroll
            for (int c = 0; c < 4; c++) acc[a][b][c] = 0.f;

    const int a_row = (lane & 7) + (((lane >> 3) & 1) << 3);
    const int a_kb  = (lane >> 4) << 3;
    const int b_n   = (lane & 7) + ((lane >> 4) << 3);
    const int b_kb  = ((lane >> 3) & 1) << 3;

    const int nchunks = K >> 6;

    auto stage = [&](int c, int s) {
        const int kc = c << 6;
        const uint32_t abase = sb + s * 49152;
        const uint32_t bbase = abase + 32768;
        // A: 256 rows x 128B = 2048 x 16B
        #pragma unroll
        for (int i = 0; i < 8; i++) {
            const int idx = i * 256 + tid;
            const int r = idx >> 3, ch = idx & 7;
            const uint32_t sw = SWZ128((uint32_t)(r * 128 + ch * 16));
            const int grow = row0 + r;
            const __half* src = A + (size_t)grow * K + kc + ch * 8;
            cp_async16(abase + sw, src, (grow < M) ? 16 : 0);
        }
        // B: 128 rows x 128B = 1024 x 16B
        #pragma unroll
        for (int i = 0; i < 4; i++) {
            const int idx = i * 256 + tid;
            const int r = idx >> 3, ch = idx & 7;
            const uint32_t sw = SWZ128((uint32_t)(r * 128 + ch * 16));
            const __half* src = Bt + (size_t)(col0 + r) * K + kc + ch * 8;
            cp_async16(bbase + sw, src, 16);
        }
    };

    stage(0, 0); CP_COMMIT();
    if (nchunks > 1) stage(1, 1);
    CP_COMMIT();

    for (int c = 0; c < nchunks; c++) {
        CP_WAIT1();
        __syncthreads();
        const int s = c & 1;
        const uint32_t abase = sb + s * 49152;
        const uint32_t bbase = abase + 32768;
        #pragma unroll
        for (int ks = 0; ks < 4; ks++) {
            uint32_t ah[4][4];
            #pragma unroll
            for (int mt = 0; mt < 4; mt++) {
                const int rrow = wr * 64 + mt * 16 + a_row;
                const uint32_t off = SWZ128((uint32_t)(rrow * 128 + (ks * 16 + a_kb) * 2));
                ldsm_x4(ah[mt], abase + off);
            }
            #pragma unroll
            for (int nt2 = 0; nt2 < 4; nt2++) {
                uint32_t bh[4];
                const int nrow = wc * 64 + nt2 * 16 + b_n;
                const uint32_t off = SWZ128((uint32_t)(nrow * 128 + (ks * 16 + b_kb) * 2));
                ldsm_x4(bh, bbase + off);
                #pragma unroll
                for (int mt = 0; mt < 4; mt++) {
                    mma16816h(acc[mt][nt2 * 2 + 0], ah[mt], bh);
                    mma16816h(acc[mt][nt2 * 2 + 1], ah[mt], bh + 2);
                }
            }
        }
        __syncthreads();
        if (c + 2 < nchunks) stage(c + 2, s);
        CP_COMMIT();
    }

    if (EPI == 1 || EPI == 4) {
        // direct fragment stores (no SMEM roundtrip)
        #pragma unroll
        for (int mt = 0; mt < 4; mt++) {
            const int r0g = row0 + wr * 64 + mt * 16 + (lane >> 2);
            #pragma unroll
            for (int nt = 0; nt < 8; nt++) {
                const int cg = col0 + wc * 64 + nt * 8 + ((lane & 3) << 1);
                const float b0 = __ldg(&bias[cg + 0]);
                const float b1 = __ldg(&bias[cg + 1]);
                float v00 = acc[mt][nt][0] + b0, v01 = acc[mt][nt][1] + b1;
                float v10 = acc[mt][nt][2] + b0, v11 = acc[mt][nt][3] + b1;
                if (EPI == 1) {
                    if (r0g < M)
                        *(__half2*)(OutH + (size_t)r0g * N + cg) =
                            __floats2half2_rn(gelu_f(v00), gelu_f(v01));
                    if (r0g + 8 < M)
                        *(__half2*)(OutH + (size_t)(r0g + 8) * N + cg) =
                            __floats2half2_rn(gelu_f(v10), gelu_f(v11));
                } else {
                    if (col0 >= 1024) {
                        const int cl = cg - 1024;
                        if (r0g < M)
                            *(float2*)(OutXr + (size_t)r0g * 128 + cl) =
                                make_float2(v00, v01);
                        if (r0g + 8 < M)
                            *(float2*)(OutXr + (size_t)(r0g + 8) * 128 + cl) =
                                make_float2(v10, v11);
                    } else {
                        if (r0g < M)
                            *(__half2*)(OutH + (size_t)r0g * KVDIM + cg) =
                                __floats2half2_rn(v00, v01);
                        if (r0g + 8 < M)
                            *(__half2*)(OutH + (size_t)(r0g + 8) * KVDIM + cg) =
                                __floats2half2_rn(v10, v11);
                    }
                }
            }
        }
    } else {
        // dump accumulators to SMEM Cs (256 x 132)
        #pragma unroll
        for (int mt = 0; mt < 4; mt++)
            #pragma unroll
            for (int nt = 0; nt < 8; nt++)
                #pragma unroll
                for (int i = 0; i < 4; i++) {
                    const int r = wr * 64 + mt * 16 + (lane >> 2) + ((i >> 1) << 3);
                    const int cc = wc * 64 + nt * 8 + ((lane & 3) << 1) + (i & 1);
                    Cs[r * 132 + cc] = acc[mt][nt][i];
                }
        __syncthreads();
        // warp-per-row LN: 8 warps x 32 rows
        const float4 b4 = *(const float4*)&bias[lane * 4];
        const float4 sv = *(const float4*)&lns[lane * 4];
        const float4 bv = *(const float4*)&lnb[lane * 4];
        const float gs = (EPI == 2) ? *gscale : 0.f;
        #pragma unroll 4
        for (int j = 0; j < 32; j++) {
            const int r = wid * 32 + j;
            const int row = row0 + r;
            if (row >= M) break;
            const float4 a4 = *(const float4*)&Cs[r * 132 + lane * 4];
            float r0 = a4.x + b4.x, r1 = a4.y + b4.y;
            float r2 = a4.z + b4.z, r3 = a4.w + b4.w;
            if (EPI == 2) {
                const float4 h4 = *(const float4*)&C[(size_t)row * 128 + lane * 4];
                r0 = h4.x + gs * r0; r1 = h4.y + gs * r1;
                r2 = h4.z + gs * r2; r3 = h4.w + gs * r3;
            }
            *(float4*)&C[(size_t)row * 128 + lane * 4] = make_float4(r0, r1, r2, r3);
            float s1 = r0 + r1 + r2 + r3;
            float s2 = r0 * r0 + r1 * r1 + r2 * r2 + r3 * r3;
            #pragma unroll
            for (int off = 16; off > 0; off >>= 1) {
                s1 += __shfl_xor_sync(0xffffffffu, s1, off);
                s2 += __shfl_xor_sync(0xffffffffu, s2, off);
            }
            const float mean = s1 * (1.f / 128.f);
            const float var = s2 * (1.f / 128.f) - mean * mean;
            const float inv = rsqrtf(var + 1e-5f);
            const float o0 = (r0 - mean) * inv * sv.x + bv.x;
            const float o1 = (r1 - mean) * inv * sv.y + bv.y;
            const float o2 = (r2 - mean) * inv * sv.z + bv.z;
            const float o3 = (r3 - mean) * inv * sv.w + bv.w;
            if (EPI == 2 && OutF) {
                *(float4*)&OutF[(size_t)row * 128 + lane * 4] = make_float4(o0, o1, o2, o3);
            } else {
                __half2 p01 = __floats2half2_rn(o0, o1);
                __half2 p23 = __floats2half2_rn(o2, o3);
                __half2* ph = (__half2*)(OutH + (size_t)row * 128 + lane * 4);
                ph[0] = p01; ph[1] = p23;
            }
        }
    }
}

// ---------------- fused attention (q = hn fp16; keff/v fp16) ----------------
__global__ void __launch_bounds__(128) attn_fused_kernel(
    const float* __restrict__ Wb, const float* __restrict__ g1p,
    const float* __restrict__ lns, const float* __restrict__ lnb)
{
    __shared__ float sm[4][128];
    __shared__ float ssbuf[4];
    __shared__ float red[4];
    __shared__ float red2[4][2];
    const int node = blockIdx.x;
    const int warp = threadIdx.x >> 5, lane = threadIdx.x & 31;
    const int beg = g_indptr[node], end = g_indptr[node + 1];
    const int hb = warp * 128 + lane * 4;
    const float4 qv = h4_to_f4(*(const uint2*)(g_ah + (size_t)node * 128 + lane * 4));
    float ss = 0.f, ax = 0.f, ay = 0.f, az = 0.f, aw = 0.f;
    int i = beg;
    for (; i + 4 <= end; i += 4) {
        const int s0 = g_csrc[i], s1 = g_csrc[i + 1];
        const int s2 = g_csrc[i + 2], s3 = g_csrc[i + 3];
        const float4 k0 = h4_to_f4(*(const uint2*)(g_kvh + (size_t)s0 * KVDIM + hb));
        const float4 k1 = h4_to_f4(*(const uint2*)(g_kvh + (size_t)s1 * KVDIM + hb));
        const float4 k2 = h4_to_f4(*(const uint2*)(g_kvh + (size_t)s2 * KVDIM + hb));
        const float4 k3 = h4_to_f4(*(const uint2*)(g_kvh + (size_t)s3 * KVDIM + hb));
        float d0 = qv.x * k0.x + qv.y * k0.y + qv.z * k0.z + qv.w * k0.w;
        float d1 = qv.x * k1.x + qv.y * k1.y + qv.z * k1.z + qv.w * k1.w;
        float d2 = qv.x * k2.x + qv.y * k2.y + qv.z * k2.z + qv.w * k2.w;
        float d3 = qv.x * k3.x + qv.y * k3.y + qv.z * k3.z + qv.w * k3.w;
        const float4 v0 = h4_to_f4(*(const uint2*)(g_kvh + (size_t)s0 * KVDIM + 512 + hb));
        const float4 v1 = h4_to_f4(*(const uint2*)(g_kvh + (size_t)s1 * KVDIM + 512 + hb));
        const float4 v2 = h4_to_f4(*(const uint2*)(g_kvh + (size_t)s2 * KVDIM + 512 + hb));
        const float4 v3 = h4_to_f4(*(const uint2*)(g_kvh + (size_t)s3 * KVDIM + 512 + hb));
        const float w0 = g_wb[s0 * 4 + warp], w1 = g_wb[s1 * 4 + warp];
        const float w2 = g_wb[s2 * 4 + warp], w3 = g_wb[s3 * 4 + warp];
        #pragma unroll
        for (int off = 16; off > 0; off >>= 1) {
            d0 += __shfl_xor_sync(0xffffffffu, d0, off);
            d1 += __shfl_xor_sync(0xffffffffu, d1, off);
            d2 += __shfl_xor_sync(0xffffffffu, d2, off);
            d3 += __shfl_xor_sync(0xffffffffu, d3, off);
        }
        const float p0 = __expf(d0 + w0), p1 = __expf(d1 + w1);
        const float p2 = __expf(d2 + w2), p3 = __expf(d3 + w3);
        ss += (p0 + p1) + (p2 + p3);
        ax += p0 * v0.x + p1 * v1.x + p2 * v2.x + p3 * v3.x;
        ay += p0 * v0.y + p1 * v1.y + p2 * v2.y + p3 * v3.y;
        az += p0 * v0.z + p1 * v1.z + p2 * v2.z + p3 * v3.z;
        aw += p0 * v0.w + p1 * v1.w + p2 * v2.w + p3 * v3.w;
    }
    for (; i < end; i++) {
        const int s0 = g_csrc[i];
        const float4 k0 = h4_to_f4(*(const uint2*)(g_kvh + (size_t)s0 * KVDIM + hb));
        float d0 = qv.x * k0.x + qv.y * k0.y + qv.z * k0.z + qv.w * k0.w;
        const float w0 = g_wb[s0 * 4 + warp];
        #pragma unroll
        for (int off = 16; off > 0; off >>= 1)
            d0 += __shfl_xor_sync(0xffffffffu, d0, off);
        const float p0 = __expf(d0 + w0);
        const float4 v0 = h4_to_f4(*(const uint2*)(g_kvh + (size_t)s0 * KVDIM + 512 + hb));
        ss += p0;
        ax += p0 * v0.x; ay += p0 * v0.y; az += p0 * v0.z; aw += p0 * v0.w;
    }
    *(float4*)&sm[warp][lane * 4] = make_float4(ax, ay, az, aw);
    if (lane == 0) ssbuf[warp] = ss;
    __syncthreads();

    const int t = threadIdx.x;
    const float i0 = ssbuf[0] > 0.f ? 1.f / ssbuf[0] : 0.f;
    const float i1 = ssbuf[1] > 0.f ? 1.f / ssbuf[1] : 0.f;
    const float i2 = ssbuf[2] > 0.f ? 1.f / ssbuf[2] : 0.f;
    const float i3 = ssbuf[3] > 0.f ? 1.f / ssbuf[3] : 0.f;
    const float out = 0.25f * (sm[0][t] * i0 + sm[1][t] * i1 +
                               sm[2][t] * i2 + sm[3][t] * i3);
    const float xr = g_xr[(size_t)node * 128 + t];
    float p = out * __ldg(&Wb[t]) + xr * __ldg(&Wb[128 + t]) +
              (out - xr) * __ldg(&Wb[256 + t]);
    #pragma unroll
    for (int off = 16; off > 0; off >>= 1)
        p += __shfl_xor_sync(0xffffffffu, p, off);
    if (lane == 0) red[warp] = p;
    __syncthreads();
    const float logit = red[0] + red[1] + red[2] + red[3];
    const float beta = 1.f / (1.f + __expf(-logit));
    const float g = *g1p;
    const float hn = g_h[(size_t)node * 128 + t] +
                     g * (beta * xr + (1.f - beta) * out);
    g_h[(size_t)node * 128 + t] = hn;
    float s1 = hn, s2 = hn * hn;
    #pragma unroll
    for (int off = 16; off > 0; off >>= 1) {
        s1 += __shfl_xor_sync(0xffffffffu, s1, off);
        s2 += __shfl_xor_sync(0xffffffffu, s2, off);
    }
    if (lane == 0) { red2[warp][0] = s1; red2[warp][1] = s2; }
    __syncthreads();
    const float S1 = red2[0][0] + red2[1][0] + red2[2][0] + red2[3][0];
    const float S2 = red2[0][1] + red2[1][1] + red2[2][1] + red2[3][1];
    const float mean = S1 * (1.f / 128.f);
    const float var = S2 * (1.f / 128.f) - mean * mean;
    const float o = (hn - mean) * rsqrtf(var + 1e-5f) * __ldg(&lns[t]) + __ldg(&lnb[t]);
    g_ah[(size_t)node * 128 + t] = __float2half_rn(o);
}

// ---------------- host launch ----------------
extern "C" void kernel_launch(void* const* d_in, const int* in_sizes, int n_in,
                              void* d_out, int out_size) {
    (void)in_sizes; (void)n_in; (void)out_size;
    const float* x     = (const float*)d_in[0];
    const int*   ei    = (const int*)d_in[1];
    const float* Win   = (const float*)d_in[2];
    const float* b_in  = (const float*)d_in[3];
    const float* ln1_s = (const float*)d_in[4];
    const float* ln1_b = (const float*)d_in[5];
    const float* Wq    = (const float*)d_in[6];
    const float* bq    = (const float*)d_in[7];
    const float* Wk    = (const float*)d_in[8];
    const float* bk    = (const float*)d_in[9];
    const float* Wv    = (const float*)d_in[10];
    const float* bv    = (const float*)d_in[11];
    const float* Wskip = (const float*)d_in[12];
    const float* bskip = (const float*)d_in[13];
    const float* Wbeta = (const float*)d_in[14];
    const float* ln2_s = (const float*)d_in[15];
    const float* ln2_b = (const float*)d_in[16];
    const float* W1    = (const float*)d_in[17];
    const float* b1    = (const float*)d_in[18];
    const float* W2    = (const float*)d_in[19];
    const float* b2    = (const float*)d_in[20];
    const float* g1    = (const float*)d_in[21];
    const float* g2    = (const float*)d_in[22];
    const float* lno_s = (const float*)d_in[23];
    const float* lno_b = (const float*)d_in[24];
    (void)bk;

    float *h, *xr, *bkvs, *bvec;
    __half *kvh, *ah, *mh, *xh, *wh;
    cudaGetSymbolAddress((void**)&h,    g_h);
    cudaGetSymbolAddress((void**)&kvh,  g_kvh);
    cudaGetSymbolAddress((void**)&xr,   g_xr);
    cudaGetSymbolAddress((void**)&bkvs, g_bkvs);
    cudaGetSymbolAddress((void**)&bvec, g_bvec);
    cudaGetSymbolAddress((void**)&ah,   g_ah);
    cudaGetSymbolAddress((void**)&mh,   g_mh);
    cudaGetSymbolAddress((void**)&xh,   g_xh);
    cudaGetSymbolAddress((void**)&wh,   g_wh);

    static bool attr_done = false;
    if (!attr_done) {
        cudaFuncSetAttribute(mma_gemm_kernel<1>, cudaFuncAttributeMaxDynamicSharedMemorySize, MG_SMEM_LN);
        cudaFuncSetAttribute(mma_gemm_kernel<2>, cudaFuncAttributeMaxDynamicSharedMemorySize, MG_SMEM_LN);
        cudaFuncSetAttribute(mma_gemm_kernel<3>, cudaFuncAttributeMaxDynamicSharedMemorySize, MG_SMEM_LN);
        cudaFuncSetAttribute(mma_gemm_kernel<4>, cudaFuncAttributeMaxDynamicSharedMemorySize, MG_SMEM_LN);
        attr_done = true;
    }

    const int MROWS = (N_NODES + 255) / 256;  // 79

    // [0] G = scale*WqWk^T (+ bvec)
    gmat_kernel<<<(131072 + 1024 + 255) / 256, 256>>>(Wq, Wk, bq);
    // [1] pack fp16 weights + biases + x
    prep_all<<<(PREP_TOTAL + 255) / 256, 256>>>(Wv, Wskip, W1, W2, Win, bv, bskip, x);
    // [2] input projection + LN1(layer0) fused (K=64, 1 chunk)
    mma_gemm_kernel<3><<<dim3(1, MROWS), 256, MG_SMEM_LN>>>(
        xh, wh + W_WIN_OFF, b_in, h, nullptr,
        ah, nullptr, ln1_s, ln1_b, nullptr, N_NODES, 128, 64);
    // [3] layer-0 kvs GEMM  (ncu capture slot)
    mma_gemm_kernel<4><<<dim3(9, MROWS), 256, MG_SMEM_PIPE>>>(
        ah, wh, bkvs, nullptr, nullptr,
        kvh, nullptr, nullptr, nullptr, xr, N_NODES, KVS_N, 128);
    // CSR build
    zero_cnt_kernel<<<(N_NODES + 255) / 256, 256>>>();
    deg_kernel<<<(N_EDGES + 255) / 256, 256>>>(ei);
    scan_kernel<<<1, 1024>>>();
    scatter_kernel<<<(N_EDGES + 255) / 256, 256>>>(ei);

    for (int l = 0; l < 2; l++) {
        const int wb = l * W_PER_LAYER;
        if (l == 1) {
            mma_gemm_kernel<4><<<dim3(9, MROWS), 256, MG_SMEM_PIPE>>>(
                ah, wh + wb, bkvs + l * KVS_N, nullptr, nullptr,
                kvh, nullptr, nullptr, nullptr, xr, N_NODES, KVS_N, 128);
        }
        // logit bias term (bq . Wk hn_s) per node/head
        wb_kernel<<<(N_NODES * 4 + 255) / 256, 256>>>(bvec + l * 512);
        // attention + beta + residual + LN2 + fp16 out
        attn_fused_kernel<<<N_NODES, 128>>>(Wbeta + l * 384, g1 + l,
                                            ln2_s + l * 128, ln2_b + l * 128);
        // FFN1 (gelu -> fp16 mid)
        mma_gemm_kernel<1><<<dim3(4, MROWS), 256, MG_SMEM_PIPE>>>(
            ah, wh + wb + WL_W1, b1 + l * 512, nullptr, nullptr,
            mh, nullptr, nullptr, nullptr, nullptr, N_NODES, 512, 128);
        // FFN2 + residual + LN (next layer ln1, or final lno -> d_out)
        if (l == 0) {
            mma_gemm_kernel<2><<<dim3(1, MROWS), 256, MG_SMEM_LN>>>(
                mh, wh + wb + WL_W2, b2 + l * 128, h, g2 + l,
                ah, nullptr, ln1_s + 128, ln1_b + 128, nullptr,
                N_NODES, 128, 512);
        } else {
            mma_gemm_kernel<2><<<dim3(1, MROWS), 256, MG_SMEM_LN>>>(
                mh, wh + wb + WL_W2, b2 + l * 128, h, g2 + l,
                nullptr, (float*)d_out, lno_s, lno_b, nullptr,
                N_NODES, 128, 512);
        }
    }
}

// round 12
// speedup vs baseline: 1.7549x; 1.7549x over previous
#include <cuda_runtime.h>
#include <cuda_bf16.h>
#include <cuda_fp16.h>
#include <math.h>
#include <stdint.h>

#define N_NODES 20000
#define N_EDGES 320000
#define FDIM 32
#define HDIM 128
#define NHEADS 4
#define KVDIM 1024    // fused keff|v row (fp16)

// ---------------- device-global scratch ----------------
__device__ float g_h[N_NODES * HDIM];
__device__ __half g_kvh[N_NODES * KVDIM];
__device__ float g_xr[N_NODES * HDIM];
__device__ float g_wb[N_NODES * NHEADS];
__device__ int   g_indptr[N_NODES + 1];
__device__ int   g_cnt[N_NODES];
__device__ int   g_cursor[N_NODES];
__device__ int   g_csrc[N_EDGES];
// fp16 activation buffers
__device__ __half g_ah[N_NODES * HDIM];    // hn (LN output)
__device__ __half g_mh[N_NODES * 512];     // FFN mid
__device__ __half g_xh[N_NODES * 64];      // padded input
// G = scale * Wq Wk^T per head (B-layout [n=h*128+i][k=j]) + bvec
__device__ float g_G[2 * 512 * 128];
__device__ float g_bvec[2 * 4 * 128];
// packed transposed fp16 weights
#define WL_KEFF 0
#define WL_V    65536
#define WL_SKIP 131072
#define WL_W1   147456
#define WL_W2   212992
#define W_PER_LAYER 278528
#define W_WIN_OFF 557056
#define W_TOTAL 565248
#define KVS_N 1152
#define PREP_TOTAL (W_TOTAL + 2 * KVS_N + N_NODES * 64)
__device__ __half g_wh[W_TOTAL];
__device__ float g_bkvs[2 * KVS_N];

// ---------------- helpers ----------------
__device__ __forceinline__ uint32_t smem_to_u32(const void* p) {
    uint32_t a;
    asm("{ .reg .u64 t; cvta.to.shared.u64 t, %1; cvt.u32.u64 %0, t; }"
        : "=r"(a) : "l"(p));
    return a;
}
#define SWZ128(bo) ((bo) ^ (((bo) >> 3) & 0x70))

__device__ __forceinline__ void cp_async16(uint32_t dst, const void* src, int szbytes) {
    asm volatile("cp.async.cg.shared.global [%0], [%1], 16, %2;"
        :: "r"(dst), "l"(src), "r"(szbytes));
}
#define CP_COMMIT() asm volatile("cp.async.commit_group;" ::: "memory")
#define CP_WAIT1()  asm volatile("cp.async.wait_group 1;" ::: "memory")

__device__ __forceinline__ void ldsm_x4(uint32_t* r, uint32_t addr) {
    asm volatile("ldmatrix.sync.aligned.m8n8.x4.shared.b16 {%0,%1,%2,%3}, [%4];"
        : "=r"(r[0]), "=r"(r[1]), "=r"(r[2]), "=r"(r[3]) : "r"(addr));
}
__device__ __forceinline__ void mma16816h(float* c, const uint32_t* a, const uint32_t* b) {
    asm volatile("mma.sync.aligned.m16n8k16.row.col.f32.f16.f16.f32 "
        "{%0,%1,%2,%3}, {%4,%5,%6,%7}, {%8,%9}, {%0,%1,%2,%3};"
        : "+f"(c[0]), "+f"(c[1]), "+f"(c[2]), "+f"(c[3])
        : "r"(a[0]), "r"(a[1]), "r"(a[2]), "r"(a[3]), "r"(b[0]), "r"(b[1]));
}
__device__ __forceinline__ float gelu_f(float x) {
    return 0.5f * x * (1.0f + erff(x * 0.70710678118654752f));
}
__device__ __forceinline__ float4 h4_to_f4(uint2 raw) {
    const __half2 h0 = *reinterpret_cast<__half2*>(&raw.x);
    const __half2 h1 = *reinterpret_cast<__half2*>(&raw.y);
    const float2 a = __half22float2(h0);
    const float2 b = __half22float2(h1);
    return make_float4(a.x, a.y, b.x, b.y);
}

// ---------------- G precompute: G_h = scale*Wq_h Wk_h^T, bvec ----------------
__global__ void gmat_kernel(const float* __restrict__ Wq,
                            const float* __restrict__ Wk,
                            const float* __restrict__ bq)
{
    const float scale = 0.08838834764831845f;
    int idx = blockIdx.x * blockDim.x + threadIdx.x;
    if (idx < 131072) {
        const int l = idx >> 16, r = idx & 65535;
        const int n = r >> 7, k = r & 127;
        const int hh = n >> 7, i = n & 127;
        const float4* wq = (const float4*)(Wq + l * 65536 + i * 512 + hh * 128);
        const float4* wk = (const float4*)(Wk + l * 65536 + k * 512 + hh * 128);
        float s = 0.f;
        #pragma unroll 8
        for (int a = 0; a < 32; a++) {
            const float4 qa = __ldg(&wq[a]);
            const float4 ka = __ldg(&wk[a]);
            s += qa.x * ka.x + qa.y * ka.y + qa.z * ka.z + qa.w * ka.w;
        }
        g_G[idx] = s * scale;
    } else if (idx < 131072 + 1024) {
        const int r = idx - 131072;
        const int l = r >> 9, r2 = r & 511;
        const int hh = r2 >> 7, j = r2 & 127;
        const float* b = bq + l * 512 + hh * 128;
        const float* wk = Wk + l * 65536 + j * 512 + hh * 128;
        float s = 0.f;
        for (int a = 0; a < 128; a++) s += __ldg(&b[a]) * __ldg(&wk[a]);
        g_bvec[r] = s * scale;
    }
}

// ---------------- one-shot packer: fp16 weights + biases + x ----------------
__global__ void prep_all(
    const float* __restrict__ Wv, const float* __restrict__ Wskip,
    const float* __restrict__ W1, const float* __restrict__ W2,
    const float* __restrict__ Win,
    const float* __restrict__ bv, const float* __restrict__ bskip,
    const float* __restrict__ x)
{
    int idx = blockIdx.x * blockDim.x + threadIdx.x;
    if (idx >= PREP_TOTAL) return;
    if (idx >= W_TOTAL + 2 * KVS_N) {
        const int r = idx - (W_TOTAL + 2 * KVS_N);
        const int row = r >> 6, k = r & 63;
        const float val = (k < 32) ? __ldg(&x[row * 32 + k]) : 0.f;
        g_xh[r] = __float2half_rn(val);
        return;
    }
    if (idx >= W_TOTAL) {
        const int r = idx - W_TOTAL;
        const int l = r / KVS_N, c = r % KVS_N;
        g_bkvs[r] = (c < 512)  ? 0.f
                  : (c < 1024) ? __ldg(&bv[l * 512 + c - 512])
                               : __ldg(&bskip[l * 128 + c - 1024]);
        return;
    }
    float val;
    if (idx < W_WIN_OFF) {
        const int l = idx / W_PER_LAYER, r = idx % W_PER_LAYER;
        if (r < WL_V) {
            val = g_G[l * 65536 + r];
        } else if (r < WL_SKIP) {
            const int r2 = r - WL_V, n = r2 / 128, k = r2 % 128;
            val = __ldg(&Wv[l * 65536 + k * 512 + n]);
        } else if (r < WL_W1) {
            const int r3 = r - WL_SKIP, n = r3 / 128, k = r3 % 128;
            val = __ldg(&Wskip[l * 16384 + k * 128 + n]);
        } else if (r < WL_W2) {
            const int r4 = r - WL_W1, n = r4 / 128, k = r4 % 128;
            val = __ldg(&W1[l * 65536 + k * 512 + n]);
        } else {
            const int r5 = r - WL_W2, n = r5 / 512, k = r5 % 512;
            val = __ldg(&W2[l * 65536 + k * 128 + n]);
        }
    } else {
        const int r6 = idx - W_WIN_OFF, n = r6 / 64, k = r6 % 64;
        val = (k < 32) ? __ldg(&Win[k * 128 + n]) : 0.f;
    }
    g_wh[idx] = __float2half_rn(val);
}

// ---------------- CSR build ----------------
__global__ void zero_cnt_kernel() {
    int i = blockIdx.x * blockDim.x + threadIdx.x;
    if (i < N_NODES) g_cnt[i] = 0;
}
__global__ void deg_kernel(const int* __restrict__ ei) {
    int e = blockIdx.x * blockDim.x + threadIdx.x;
    if (e < N_EDGES) atomicAdd(&g_cnt[ei[N_EDGES + e]], 1);
}
__global__ void scan_kernel() {
    __shared__ int wsum[32];
    __shared__ int carry;
    const int tid = threadIdx.x, lane = tid & 31, wid = tid >> 5;
    if (tid == 0) { carry = 0; g_indptr[0] = 0; }
    __syncthreads();
    for (int base = 0; base < N_NODES; base += 1024) {
        int i = base + tid;
        int v = (i < N_NODES) ? g_cnt[i] : 0;
        int x = v;
        #pragma unroll
        for (int off = 1; off < 32; off <<= 1) {
            int y = __shfl_up_sync(0xffffffffu, x, off);
            if (lane >= off) x += y;
        }
        if (lane == 31) wsum[wid] = x;
        __syncthreads();
        if (wid == 0) {
            int w = wsum[lane];
            #pragma unroll
            for (int off = 1; off < 32; off <<= 1) {
                int y = __shfl_up_sync(0xffffffffu, w, off);
                if (lane >= off) w += y;
            }
            wsum[lane] = w;
        }
        __syncthreads();
        int incl = carry + (wid > 0 ? wsum[wid - 1] : 0) + x;
        if (i < N_NODES) {
            g_indptr[i + 1] = incl;
            g_cursor[i] = incl - v;
        }
        __syncthreads();
        if (tid == 1023) carry = incl;
        __syncthreads();
    }
}
__global__ void scatter_kernel(const int* __restrict__ ei) {
    int e = blockIdx.x * blockDim.x + threadIdx.x;
    if (e < N_EDGES) {
        int s = ei[e];
        int d = ei[N_EDGES + e];
        int pos = atomicAdd(&g_cursor[d], 1);
        g_csrc[pos] = s;
    }
}

// ---------------- wb: per-node bias term hn_s . bvec_h ----------------
__global__ void wb_kernel(const float* __restrict__ bvec) {
    int t = blockIdx.x * blockDim.x + threadIdx.x;
    if (t >= N_NODES * NHEADS) return;
    const int node = t >> 2, hh = t & 3;
    const float* bv = bvec + hh * 128;
    float s = 0.f;
    #pragma unroll 8
    for (int j = 0; j < 32; j++) {
        const float4 a = h4_to_f4(*(const uint2*)(g_ah + (size_t)node * 128 + j * 4));
        const float4 w = *(const float4*)(bv + j * 4);
        s += a.x * w.x + a.y * w.y + a.z * w.z + a.w * w.w;
    }
    g_wb[t] = s;
}

// ---------------- fp16 HMMA GEMM, cp.async 2-stage, K-chunk 64 ----------------
// 256 threads, 8 warps (4 row x 2 col groups), warp tile 32x64, CTA 128x128.
// SMEM: stage = A 16KB + B 16KB; 2 stages = 64KB.
// EPI 1/4: DIRECT fragment stores (no SMEM roundtrip).
// EPI 2/3: Cs 128x132 f32 + fused LN (N==128, grid.x==1).
#define MG_SMEM_BYTES (128 * 132 * 4)

template <int EPI>
__global__ void __launch_bounds__(256, 2) mma_gemm_kernel(
    const __half* __restrict__ A, const __half* __restrict__ Bt,
    const float* __restrict__ bias, float* __restrict__ C,
    const float* __restrict__ gscale,
    __half* __restrict__ OutH, float* __restrict__ OutF,
    const float* __restrict__ lns, const float* __restrict__ lnb,
    float* __restrict__ OutXr,
    int M, int N, int K)
{
    extern __shared__ char smem[];
    float* Cs = (float*)smem;
    const int tid = threadIdx.x;
    const int wid = tid >> 5, lane = tid & 31;
    const int wr = wid & 3, wc = wid >> 2;
    const int row0 = blockIdx.y * 128, col0 = blockIdx.x * 128;
    const uint32_t sb = smem_to_u32(smem);

    float acc[2][8][4];
    #pragma unroll
    for (int a = 0; a < 2; a++)
        #pragma unroll
        for (int b = 0; b < 8; b++)
            #pragma unroll
            for (int c = 0; c < 4; c++) acc[a][b][c] = 0.f;

    const int a_row = (lane & 7) + (((lane >> 3) & 1) << 3);
    const int a_kb  = (lane >> 4) << 3;
    const int b_n   = (lane & 7) + ((lane >> 4) << 3);
    const int b_kb  = ((lane >> 3) & 1) << 3;

    const int nchunks = K >> 6;

    auto stage = [&](int c, int s) {
        const int kc = c << 6;
        const uint32_t abase = sb + s * 32768;
        const uint32_t bbase = abase + 16384;
        #pragma unroll
        for (int i = 0; i < 4; i++) {
            const int idx = i * 256 + tid;
            const int r = idx >> 3, ch = idx & 7;
            const uint32_t sw = SWZ128((uint32_t)(r * 128 + ch * 16));
            {
                const int grow = row0 + r;
                const __half* src = A + (size_t)grow * K + kc + ch * 8;
                cp_async16(abase + sw, src, (grow < M) ? 16 : 0);
            }
            {
                const __half* src = Bt + (size_t)(col0 + r) * K + kc + ch * 8;
                cp_async16(bbase + sw, src, 16);
            }
        }
    };

    stage(0, 0); CP_COMMIT();
    if (nchunks > 1) stage(1, 1);
    CP_COMMIT();

    for (int c = 0; c < nchunks; c++) {
        CP_WAIT1();
        __syncthreads();
        const int s = c & 1;
        const uint32_t abase = sb + s * 32768;
        const uint32_t bbase = abase + 16384;
        #pragma unroll
        for (int ks = 0; ks < 4; ks++) {
            uint32_t ah[2][4];
            #pragma unroll
            for (int mt = 0; mt < 2; mt++) {
                const int rrow = wr * 32 + mt * 16 + a_row;
                const uint32_t off = SWZ128((uint32_t)(rrow * 128 + (ks * 16 + a_kb) * 2));
                ldsm_x4(ah[mt], abase + off);
            }
            #pragma unroll
            for (int nt2 = 0; nt2 < 4; nt2++) {
                uint32_t bh[4];
                const int nrow = wc * 64 + nt2 * 16 + b_n;
                const uint32_t off = SWZ128((uint32_t)(nrow * 128 + (ks * 16 + b_kb) * 2));
                ldsm_x4(bh, bbase + off);
                #pragma unroll
                for (int mt = 0; mt < 2; mt++) {
                    mma16816h(acc[mt][nt2 * 2 + 0], ah[mt], bh);
                    mma16816h(acc[mt][nt2 * 2 + 1], ah[mt], bh + 2);
                }
            }
        }
        __syncthreads();
        if (c + 2 < nchunks) stage(c + 2, s);
        CP_COMMIT();
    }

    if (EPI == 1 || EPI == 4) {
        // direct fragment stores (no SMEM roundtrip)
        #pragma unroll
        for (int mt = 0; mt < 2; mt++) {
            const int r0g = row0 + wr * 32 + mt * 16 + (lane >> 2);
            #pragma unroll
            for (int nt = 0; nt < 8; nt++) {
                const int cg = col0 + wc * 64 + nt * 8 + ((lane & 3) << 1);
                const float b0 = __ldg(&bias[cg + 0]);
                const float b1 = __ldg(&bias[cg + 1]);
                float v00 = acc[mt][nt][0] + b0, v01 = acc[mt][nt][1] + b1;
                float v10 = acc[mt][nt][2] + b0, v11 = acc[mt][nt][3] + b1;
                if (EPI == 1) {
                    if (r0g < M)
                        *(__half2*)(OutH + (size_t)r0g * N + cg) =
                            __floats2half2_rn(gelu_f(v00), gelu_f(v01));
                    if (r0g + 8 < M)
                        *(__half2*)(OutH + (size_t)(r0g + 8) * N + cg) =
                            __floats2half2_rn(gelu_f(v10), gelu_f(v11));
                } else {
                    if (col0 >= 1024) {
                        const int cl = cg - 1024;
                        if (r0g < M)
                            *(float2*)(OutXr + (size_t)r0g * 128 + cl) =
                                make_float2(v00, v01);
                        if (r0g + 8 < M)
                            *(float2*)(OutXr + (size_t)(r0g + 8) * 128 + cl) =
                                make_float2(v10, v11);
                    } else {
                        if (r0g < M)
                            *(__half2*)(OutH + (size_t)r0g * KVDIM + cg) =
                                __floats2half2_rn(v00, v01);
                        if (r0g + 8 < M)
                            *(__half2*)(OutH + (size_t)(r0g + 8) * KVDIM + cg) =
                                __floats2half2_rn(v10, v11);
                    }
                }
            }
        }
    } else {
        // dump accumulators to SMEM Cs (128 x 132) then fused LN
        #pragma unroll
        for (int mt = 0; mt < 2; mt++)
            #pragma unroll
            for (int nt = 0; nt < 8; nt++)
                #pragma unroll
                for (int i = 0; i < 4; i++) {
                    const int r = wr * 32 + mt * 16 + (lane >> 2) + ((i >> 1) << 3);
                    const int cc = wc * 64 + nt * 8 + ((lane & 3) << 1) + (i & 1);
                    Cs[r * 132 + cc] = acc[mt][nt][i];
                }
        __syncthreads();
        const float4 b4 = *(const float4*)&bias[lane * 4];
        const float4 sv = *(const float4*)&lns[lane * 4];
        const float4 bv = *(const float4*)&lnb[lane * 4];
        const float gs = (EPI == 2) ? *gscale : 0.f;
        #pragma unroll 4
        for (int j = 0; j < 16; j++) {
            const int r = wid * 16 + j;
            const int row = row0 + r;
            if (row >= M) break;
            const float4 a4 = *(const float4*)&Cs[r * 132 + lane * 4];
            float r0 = a4.x + b4.x, r1 = a4.y + b4.y;
            float r2 = a4.z + b4.z, r3 = a4.w + b4.w;
            if (EPI == 2) {
                const float4 h4 = *(const float4*)&C[(size_t)row * 128 + lane * 4];
                r0 = h4.x + gs * r0; r1 = h4.y + gs * r1;
                r2 = h4.z + gs * r2; r3 = h4.w + gs * r3;
            }
            *(float4*)&C[(size_t)row * 128 + lane * 4] = make_float4(r0, r1, r2, r3);
            float s1 = r0 + r1 + r2 + r3;
            float s2 = r0 * r0 + r1 * r1 + r2 * r2 + r3 * r3;
            #pragma unroll
            for (int off = 16; off > 0; off >>= 1) {
                s1 += __shfl_xor_sync(0xffffffffu, s1, off);
                s2 += __shfl_xor_sync(0xffffffffu, s2, off);
            }
            const float mean = s1 * (1.f / 128.f);
            const float var = s2 * (1.f / 128.f) - mean * mean;
            const float inv = rsqrtf(var + 1e-5f);
            const float o0 = (r0 - mean) * inv * sv.x + bv.x;
            const float o1 = (r1 - mean) * inv * sv.y + bv.y;
            const float o2 = (r2 - mean) * inv * sv.z + bv.z;
            const float o3 = (r3 - mean) * inv * sv.w + bv.w;
            if (EPI == 2 && OutF) {
                *(float4*)&OutF[(size_t)row * 128 + lane * 4] = make_float4(o0, o1, o2, o3);
            } else {
                __half2 p01 = __floats2half2_rn(o0, o1);
                __half2 p23 = __floats2half2_rn(o2, o3);
                __half2* ph = (__half2*)(OutH + (size_t)row * 128 + lane * 4);
                ph[0] = p01; ph[1] = p23;
            }
        }
    }
}

// ---------------- fused attention (q = hn fp16; keff/v fp16) ----------------
__global__ void __launch_bounds__(128) attn_fused_kernel(
    const float* __restrict__ Wb, const float* __restrict__ g1p,
    const float* __restrict__ lns, const float* __restrict__ lnb)
{
    __shared__ float sm[4][128];
    __shared__ float ssbuf[4];
    __shared__ float red[4];
    __shared__ float red2[4][2];
    const int node = blockIdx.x;
    const int warp = threadIdx.x >> 5, lane = threadIdx.x & 31;
    const int beg = g_indptr[node], end = g_indptr[node + 1];
    const int hb = warp * 128 + lane * 4;
    const float4 qv = h4_to_f4(*(const uint2*)(g_ah + (size_t)node * 128 + lane * 4));
    float ss = 0.f, ax = 0.f, ay = 0.f, az = 0.f, aw = 0.f;
    int i = beg;
    for (; i + 4 <= end; i += 4) {
        const int s0 = g_csrc[i], s1 = g_csrc[i + 1];
        const int s2 = g_csrc[i + 2], s3 = g_csrc[i + 3];
        const float4 k0 = h4_to_f4(*(const uint2*)(g_kvh + (size_t)s0 * KVDIM + hb));
        const float4 k1 = h4_to_f4(*(const uint2*)(g_kvh + (size_t)s1 * KVDIM + hb));
        const float4 k2 = h4_to_f4(*(const uint2*)(g_kvh + (size_t)s2 * KVDIM + hb));
        const float4 k3 = h4_to_f4(*(const uint2*)(g_kvh + (size_t)s3 * KVDIM + hb));
        float d0 = qv.x * k0.x + qv.y * k0.y + qv.z * k0.z + qv.w * k0.w;
        float d1 = qv.x * k1.x + qv.y * k1.y + qv.z * k1.z + qv.w * k1.w;
        float d2 = qv.x * k2.x + qv.y * k2.y + qv.z * k2.z + qv.w * k2.w;
        float d3 = qv.x * k3.x + qv.y * k3.y + qv.z * k3.z + qv.w * k3.w;
        const float4 v0 = h4_to_f4(*(const uint2*)(g_kvh + (size_t)s0 * KVDIM + 512 + hb));
        const float4 v1 = h4_to_f4(*(const uint2*)(g_kvh + (size_t)s1 * KVDIM + 512 + hb));
        const float4 v2 = h4_to_f4(*(const uint2*)(g_kvh + (size_t)s2 * KVDIM + 512 + hb));
        const float4 v3 = h4_to_f4(*(const uint2*)(g_kvh + (size_t)s3 * KVDIM + 512 + hb));
        const float w0 = g_wb[s0 * 4 + warp], w1 = g_wb[s1 * 4 + warp];
        const float w2 = g_wb[s2 * 4 + warp], w3 = g_wb[s3 * 4 + warp];
        #pragma unroll
        for (int off = 16; off > 0; off >>= 1) {
            d0 += __shfl_xor_sync(0xffffffffu, d0, off);
            d1 += __shfl_xor_sync(0xffffffffu, d1, off);
            d2 += __shfl_xor_sync(0xffffffffu, d2, off);
            d3 += __shfl_xor_sync(0xffffffffu, d3, off);
        }
        const float p0 = __expf(d0 + w0), p1 = __expf(d1 + w1);
        const float p2 = __expf(d2 + w2), p3 = __expf(d3 + w3);
        ss += (p0 + p1) + (p2 + p3);
        ax += p0 * v0.x + p1 * v1.x + p2 * v2.x + p3 * v3.x;
        ay += p0 * v0.y + p1 * v1.y + p2 * v2.y + p3 * v3.y;
        az += p0 * v0.z + p1 * v1.z + p2 * v2.z + p3 * v3.z;
        aw += p0 * v0.w + p1 * v1.w + p2 * v2.w + p3 * v3.w;
    }
    for (; i < end; i++) {
        const int s0 = g_csrc[i];
        const float4 k0 = h4_to_f4(*(const uint2*)(g_kvh + (size_t)s0 * KVDIM + hb));
        float d0 = qv.x * k0.x + qv.y * k0.y + qv.z * k0.z + qv.w * k0.w;
        const float w0 = g_wb[s0 * 4 + warp];
        #pragma unroll
        for (int off = 16; off > 0; off >>= 1)
            d0 += __shfl_xor_sync(0xffffffffu, d0, off);
        const float p0 = __expf(d0 + w0);
        const float4 v0 = h4_to_f4(*(const uint2*)(g_kvh + (size_t)s0 * KVDIM + 512 + hb));
        ss += p0;
        ax += p0 * v0.x; ay += p0 * v0.y; az += p0 * v0.z; aw += p0 * v0.w;
    }
    *(float4*)&sm[warp][lane * 4] = make_float4(ax, ay, az, aw);
    if (lane == 0) ssbuf[warp] = ss;
    __syncthreads();

    const int t = threadIdx.x;
    const float i0 = ssbuf[0] > 0.f ? 1.f / ssbuf[0] : 0.f;
    const float i1 = ssbuf[1] > 0.f ? 1.f / ssbuf[1] : 0.f;
    const float i2 = ssbuf[2] > 0.f ? 1.f / ssbuf[2] : 0.f;
    const float i3 = ssbuf[3] > 0.f ? 1.f / ssbuf[3] : 0.f;
    const float out = 0.25f * (sm[0][t] * i0 + sm[1][t] * i1 +
                               sm[2][t] * i2 + sm[3][t] * i3);
    const float xr = g_xr[(size_t)node * 128 + t];
    float p = out * __ldg(&Wb[t]) + xr * __ldg(&Wb[128 + t]) +
              (out - xr) * __ldg(&Wb[256 + t]);
    #pragma unroll
    for (int off = 16; off > 0; off >>= 1)
        p += __shfl_xor_sync(0xffffffffu, p, off);
    if (lane == 0) red[warp] = p;
    __syncthreads();
    const float logit = red[0] + red[1] + red[2] + red[3];
    const float beta = 1.f / (1.f + __expf(-logit));
    const float g = *g1p;
    const float hn = g_h[(size_t)node * 128 + t] +
                     g * (beta * xr + (1.f - beta) * out);
    g_h[(size_t)node * 128 + t] = hn;
    float s1 = hn, s2 = hn * hn;
    #pragma unroll
    for (int off = 16; off > 0; off >>= 1) {
        s1 += __shfl_xor_sync(0xffffffffu, s1, off);
        s2 += __shfl_xor_sync(0xffffffffu, s2, off);
    }
    if (lane == 0) { red2[warp][0] = s1; red2[warp][1] = s2; }
    __syncthreads();
    const float S1 = red2[0][0] + red2[1][0] + red2[2][0] + red2[3][0];
    const float S2 = red2[0][1] + red2[1][1] + red2[2][1] + red2[3][1];
    const float mean = S1 * (1.f / 128.f);
    const float var = S2 * (1.f / 128.f) - mean * mean;
    const float o = (hn - mean) * rsqrtf(var + 1e-5f) * __ldg(&lns[t]) + __ldg(&lnb[t]);
    g_ah[(size_t)node * 128 + t] = __float2half_rn(o);
}

// ---------------- host launch ----------------
extern "C" void kernel_launch(void* const* d_in, const int* in_sizes, int n_in,
                              void* d_out, int out_size) {
    (void)in_sizes; (void)n_in; (void)out_size;
    const float* x     = (const float*)d_in[0];
    const int*   ei    = (const int*)d_in[1];
    const float* Win   = (const float*)d_in[2];
    const float* b_in  = (const float*)d_in[3];
    const float* ln1_s = (const float*)d_in[4];
    const float* ln1_b = (const float*)d_in[5];
    const float* Wq    = (const float*)d_in[6];
    const float* bq    = (const float*)d_in[7];
    const float* Wk    = (const float*)d_in[8];
    const float* bk    = (const float*)d_in[9];
    const float* Wv    = (const float*)d_in[10];
    const float* bv    = (const float*)d_in[11];
    const float* Wskip = (const float*)d_in[12];
    const float* bskip = (const float*)d_in[13];
    const float* Wbeta = (const float*)d_in[14];
    const float* ln2_s = (const float*)d_in[15];
    const float* ln2_b = (const float*)d_in[16];
    const float* W1    = (const float*)d_in[17];
    const float* b1    = (const float*)d_in[18];
    const float* W2    = (const float*)d_in[19];
    const float* b2    = (const float*)d_in[20];
    const float* g1    = (const float*)d_in[21];
    const float* g2    = (const float*)d_in[22];
    const float* lno_s = (const float*)d_in[23];
    const float* lno_b = (const float*)d_in[24];
    (void)bk;

    float *h, *xr, *bkvs, *bvec;
    __half *kvh, *ah, *mh, *xh, *wh;
    cudaGetSymbolAddress((void**)&h,    g_h);
    cudaGetSymbolAddress((void**)&kvh,  g_kvh);
    cudaGetSymbolAddress((void**)&xr,   g_xr);
    cudaGetSymbolAddress((void**)&bkvs, g_bkvs);
    cudaGetSymbolAddress((void**)&bvec, g_bvec);
    cudaGetSymbolAddress((void**)&ah,   g_ah);
    cudaGetSymbolAddress((void**)&mh,   g_mh);
    cudaGetSymbolAddress((void**)&xh,   g_xh);
    cudaGetSymbolAddress((void**)&wh,   g_wh);

    static bool attr_done = false;
    if (!attr_done) {
        cudaFuncSetAttribute(mma_gemm_kernel<1>, cudaFuncAttributeMaxDynamicSharedMemorySize, MG_SMEM_BYTES);
        cudaFuncSetAttribute(mma_gemm_kernel<2>, cudaFuncAttributeMaxDynamicSharedMemorySize, MG_SMEM_BYTES);
        cudaFuncSetAttribute(mma_gemm_kernel<3>, cudaFuncAttributeMaxDynamicSharedMemorySize, MG_SMEM_BYTES);
        cudaFuncSetAttribute(mma_gemm_kernel<4>, cudaFuncAttributeMaxDynamicSharedMemorySize, MG_SMEM_BYTES);
        attr_done = true;
    }

    const int MROWS = (N_NODES + 127) / 128;  // 157

    // [0] G = scale*WqWk^T (+ bvec)
    gmat_kernel<<<(131072 + 1024 + 255) / 256, 256>>>(Wq, Wk, bq);
    // [1] pack fp16 weights + biases + x
    prep_all<<<(PREP_TOTAL + 255) / 256, 256>>>(Wv, Wskip, W1, W2, Win, bv, bskip, x);
    // [2] input projection + LN1(layer0) fused (K=64, 1 chunk)
    mma_gemm_kernel<3><<<dim3(1, MROWS), 256, MG_SMEM_BYTES>>>(
        xh, wh + W_WIN_OFF, b_in, h, nullptr,
        ah, nullptr, ln1_s, ln1_b, nullptr, N_NODES, 128, 64);
    // [3] layer-0 kvs GEMM  (ncu capture slot)
    mma_gemm_kernel<4><<<dim3(9, MROWS), 256, MG_SMEM_BYTES>>>(
        ah, wh, bkvs, nullptr, nullptr,
        kvh, nullptr, nullptr, nullptr, xr, N_NODES, KVS_N, 128);
    // CSR build
    zero_cnt_kernel<<<(N_NODES + 255) / 256, 256>>>();
    deg_kernel<<<(N_EDGES + 255) / 256, 256>>>(ei);
    scan_kernel<<<1, 1024>>>();
    scatter_kernel<<<(N_EDGES + 255) / 256, 256>>>(ei);

    for (int l = 0; l < 2; l++) {
        const int wb = l * W_PER_LAYER;
        if (l == 1) {
            mma_gemm_kernel<4><<<dim3(9, MROWS), 256, MG_SMEM_BYTES>>>(
                ah, wh + wb, bkvs + l * KVS_N, nullptr, nullptr,
                kvh, nullptr, nullptr, nullptr, xr, N_NODES, KVS_N, 128);
        }
        // logit bias term (bq . Wk hn_s) per node/head
        wb_kernel<<<(N_NODES * 4 + 255) / 256, 256>>>(bvec + l * 512);
        // attention + beta + residual + LN2 + fp16 out
        attn_fused_kernel<<<N_NODES, 128>>>(Wbeta + l * 384, g1 + l,
                                            ln2_s + l * 128, ln2_b + l * 128);
        // FFN1 (gelu -> fp16 mid)
        mma_gemm_kernel<1><<<dim3(4, MROWS), 256, MG_SMEM_BYTES>>>(
            ah, wh + wb + WL_W1, b1 + l * 512, nullptr, nullptr,
            mh, nullptr, nullptr, nullptr, nullptr, N_NODES, 512, 128);
        // FFN2 + residual + LN (next layer ln1, or final lno -> d_out)
        if (l == 0) {
            mma_gemm_kernel<2><<<dim3(1, MROWS), 256, MG_SMEM_BYTES>>>(
                mh, wh + wb + WL_W2, b2 + l * 128, h, g2 + l,
                ah, nullptr, ln1_s + 128, ln1_b + 128, nullptr,
                N_NODES, 128, 512);
        } else {
            mma_gemm_kernel<2><<<dim3(1, MROWS), 256, MG_SMEM_BYTES>>>(
                mh, wh + wb + WL_W2, b2 + l * 128, h, g2 + l,
                nullptr, (float*)d_out, lno_s, lno_b, nullptr,
                N_NODES, 128, 512);
        }
    }
}

// round 13
// speedup vs baseline: 1.8088x; 1.0307x over previous
#include <cuda_runtime.h>
#include <cuda_bf16.h>
#include <cuda_fp16.h>
#include <math.h>
#include <stdint.h>

#define N_NODES 20000
#define N_EDGES 320000
#define FDIM 32
#define HDIM 128
#define NHEADS 4
#define QEDIM 512     // qeff row (fp16)

// ---------------- device-global scratch ----------------
__device__ float g_h[N_NODES * HDIM];
__device__ __half g_kvh[N_NODES * QEDIM];   // qeff
__device__ float g_xr[N_NODES * HDIM];
__device__ float g_wb[N_NODES * NHEADS];
__device__ int   g_indptr[N_NODES + 1];
__device__ int   g_cnt[N_NODES];
__device__ int   g_cursor[N_NODES];
__device__ int   g_csrc[N_EDGES];
// fp16 activation buffers
__device__ __half g_ah[N_NODES * HDIM];    // hn (LN output)
__device__ __half g_mh[N_NODES * 512];     // u_cat, then FFN mid
__device__ __half g_xh[N_NODES * 64];      // padded input
// G = scale * Wq Wk^T per head + bvec
__device__ float g_G[2 * 512 * 128];
__device__ float g_bvec[2 * 4 * 128];
// packed transposed fp16 weights (per layer):
//  [0,65536)        QEFF  Bt[n=h*128+i][k] = G_h[k][i]
//  [65536,81920)    SKIP  [128][128]
//  [81920,147456)   VAPP  Bt[n=i][k=h*128+j] = 0.25*Wv[j][h*128+i]
//  [147456,212992)  W1    [512][128]
//  [212992,278528)  W2    [128][512]
#define WL_QEFF 0
#define WL_SKIP 65536
#define WL_VAPP 81920
#define WL_W1   147456
#define WL_W2   212992
#define W_PER_LAYER 278528
#define W_WIN_OFF 557056
#define W_TOTAL 565248
#define KVS_N 640
#define PREP_TOTAL (W_TOTAL + 2 * KVS_N + 256 + N_NODES * 64)
__device__ __half g_wh[W_TOTAL];
__device__ float g_bkvs[2 * KVS_N];
__device__ float g_vb[2 * 128];

// ---------------- helpers ----------------
__device__ __forceinline__ uint32_t smem_to_u32(const void* p) {
    uint32_t a;
    asm("{ .reg .u64 t; cvta.to.shared.u64 t, %1; cvt.u32.u64 %0, t; }"
        : "=r"(a) : "l"(p));
    return a;
}
#define SWZ128(bo) ((bo) ^ (((bo) >> 3) & 0x70))

__device__ __forceinline__ void cp_async16(uint32_t dst, const void* src, int szbytes) {
    asm volatile("cp.async.cg.shared.global [%0], [%1], 16, %2;"
        :: "r"(dst), "l"(src), "r"(szbytes));
}
#define CP_COMMIT() asm volatile("cp.async.commit_group;" ::: "memory")
#define CP_WAIT1()  asm volatile("cp.async.wait_group 1;" ::: "memory")

__device__ __forceinline__ void ldsm_x4(uint32_t* r, uint32_t addr) {
    asm volatile("ldmatrix.sync.aligned.m8n8.x4.shared.b16 {%0,%1,%2,%3}, [%4];"
        : "=r"(r[0]), "=r"(r[1]), "=r"(r[2]), "=r"(r[3]) : "r"(addr));
}
__device__ __forceinline__ void mma16816h(float* c, const uint32_t* a, const uint32_t* b) {
    asm volatile("mma.sync.aligned.m16n8k16.row.col.f32.f16.f16.f32 "
        "{%0,%1,%2,%3}, {%4,%5,%6,%7}, {%8,%9}, {%0,%1,%2,%3};"
        : "+f"(c[0]), "+f"(c[1]), "+f"(c[2]), "+f"(c[3])
        : "r"(a[0]), "r"(a[1]), "r"(a[2]), "r"(a[3]), "r"(b[0]), "r"(b[1]));
}
__device__ __forceinline__ float gelu_f(float x) {
    return 0.5f * x * (1.0f + erff(x * 0.70710678118654752f));
}
__device__ __forceinline__ float4 h4_to_f4(uint2 raw) {
    const __half2 h0 = *reinterpret_cast<__half2*>(&raw.x);
    const __half2 h1 = *reinterpret_cast<__half2*>(&raw.y);
    const float2 a = __half22float2(h0);
    const float2 b = __half22float2(h1);
    return make_float4(a.x, a.y, b.x, b.y);
}
__device__ __forceinline__ float warp_sum(float v) {
    #pragma unroll
    for (int off = 16; off > 0; off >>= 1)
        v += __shfl_xor_sync(0xffffffffu, v, off);
    return v;
}

// ---------------- G precompute: G_h = scale*Wq_h Wk_h^T, bvec ----------------
__global__ void gmat_kernel(const float* __restrict__ Wq,
                            const float* __restrict__ Wk,
                            const float* __restrict__ bq)
{
    const float scale = 0.08838834764831845f;
    int idx = blockIdx.x * blockDim.x + threadIdx.x;
    if (idx < 131072) {
        const int l = idx >> 16, r = idx & 65535;
        const int n = r >> 7, k = r & 127;
        const int hh = n >> 7, i = n & 127;
        const float4* wq = (const float4*)(Wq + l * 65536 + i * 512 + hh * 128);
        const float4* wk = (const float4*)(Wk + l * 65536 + k * 512 + hh * 128);
        float s = 0.f;
        #pragma unroll 8
        for (int a = 0; a < 32; a++) {
            const float4 qa = __ldg(&wq[a]);
            const float4 ka = __ldg(&wk[a]);
            s += qa.x * ka.x + qa.y * ka.y + qa.z * ka.z + qa.w * ka.w;
        }
        g_G[idx] = s * scale;   // G_h[i][k]
    } else if (idx < 131072 + 1024) {
        const int r = idx - 131072;
        const int l = r >> 9, r2 = r & 511;
        const int hh = r2 >> 7, j = r2 & 127;
        const float* b = bq + l * 512 + hh * 128;
        const float* wk = Wk + l * 65536 + j * 512 + hh * 128;
        float s = 0.f;
        for (int a = 0; a < 128; a++) s += __ldg(&b[a]) * __ldg(&wk[a]);
        g_bvec[r] = s * scale;
    }
}

// ---------------- one-shot packer: fp16 weights + biases + x ----------------
__global__ void prep_all(
    const float* __restrict__ Wv, const float* __restrict__ Wskip,
    const float* __restrict__ W1, const float* __restrict__ W2,
    const float* __restrict__ Win,
    const float* __restrict__ bv, const float* __restrict__ bskip,
    const float* __restrict__ x)
{
    int idx = blockIdx.x * blockDim.x + threadIdx.x;
    if (idx >= PREP_TOTAL) return;
    if (idx >= W_TOTAL + 2 * KVS_N + 256) {
        const int r = idx - (W_TOTAL + 2 * KVS_N + 256);
        const int row = r >> 6, k = r & 63;
        const float val = (k < 32) ? __ldg(&x[row * 32 + k]) : 0.f;
        g_xh[r] = __float2half_rn(val);
        return;
    }
    if (idx >= W_TOTAL + 2 * KVS_N) {
        const int r = idx - (W_TOTAL + 2 * KVS_N);
        const int l = r >> 7, ii = r & 127;
        const float* b = bv + l * 512;
        g_vb[r] = 0.25f * (__ldg(&b[ii]) + __ldg(&b[128 + ii]) +
                           __ldg(&b[256 + ii]) + __ldg(&b[384 + ii]));
        return;
    }
    if (idx >= W_TOTAL) {
        const int r = idx - W_TOTAL;
        const int l = r / KVS_N, c = r % KVS_N;
        g_bkvs[r] = (c < 512) ? 0.f : __ldg(&bskip[l * 128 + c - 512]);
        return;
    }
    float val;
    if (idx < W_WIN_OFF) {
        const int l = idx / W_PER_LAYER, r = idx % W_PER_LAYER;
        if (r < WL_SKIP) {
            const int n = r / 128, k = r % 128;
            const int hh = n >> 7, i = n & 127;
            val = g_G[l * 65536 + (hh * 128 + k) * 128 + i];   // G_h[k][i]
        } else if (r < WL_VAPP) {
            const int r2 = r - WL_SKIP, n = r2 / 128, k = r2 % 128;
            val = __ldg(&Wskip[l * 16384 + k * 128 + n]);
        } else if (r < WL_W1) {
            const int r3 = r - WL_VAPP, n = r3 / 512, k = r3 % 512;
            const int hh = k >> 7, j = k & 127;
            val = 0.25f * __ldg(&Wv[l * 65536 + j * 512 + hh * 128 + n]);
        } else if (r < WL_W2) {
            const int r4 = r - WL_W1, n = r4 / 128, k = r4 % 128;
            val = __ldg(&W1[l * 65536 + k * 512 + n]);
        } else {
            const int r5 = r - WL_W2, n = r5 / 512, k = r5 % 512;
            val = __ldg(&W2[l * 65536 + k * 128 + n]);
        }
    } else {
        const int r6 = idx - W_WIN_OFF, n = r6 / 64, k = r6 % 64;
        val = (k < 32) ? __ldg(&Win[k * 128 + n]) : 0.f;
    }
    g_wh[idx] = __float2half_rn(val);
}

// ---------------- CSR build ----------------
__global__ void zero_cnt_kernel() {
    int i = blockIdx.x * blockDim.x + threadIdx.x;
    if (i < N_NODES) g_cnt[i] = 0;
}
__global__ void deg_kernel(const int* __restrict__ ei) {
    int e = blockIdx.x * blockDim.x + threadIdx.x;
    if (e < N_EDGES) atomicAdd(&g_cnt[ei[N_EDGES + e]], 1);
}
__global__ void scan_kernel() {
    __shared__ int wsum[32];
    __shared__ int carry;
    const int tid = threadIdx.x, lane = tid & 31, wid = tid >> 5;
    if (tid == 0) { carry = 0; g_indptr[0] = 0; }
    __syncthreads();
    for (int base = 0; base < N_NODES; base += 1024) {
        int i = base + tid;
        int v = (i < N_NODES) ? g_cnt[i] : 0;
        int x = v;
        #pragma unroll
        for (int off = 1; off < 32; off <<= 1) {
            int y = __shfl_up_sync(0xffffffffu, x, off);
            if (lane >= off) x += y;
        }
        if (lane == 31) wsum[wid] = x;
        __syncthreads();
        if (wid == 0) {
            int w = wsum[lane];
            #pragma unroll
            for (int off = 1; off < 32; off <<= 1) {
                int y = __shfl_up_sync(0xffffffffu, w, off);
                if (lane >= off) w += y;
            }
            wsum[lane] = w;
        }
        __syncthreads();
        int incl = carry + (wid > 0 ? wsum[wid - 1] : 0) + x;
        if (i < N_NODES) {
            g_indptr[i + 1] = incl;
            g_cursor[i] = incl - v;
        }
        __syncthreads();
        if (tid == 1023) carry = incl;
        __syncthreads();
    }
}
__global__ void scatter_kernel(const int* __restrict__ ei) {
    int e = blockIdx.x * blockDim.x + threadIdx.x;
    if (e < N_EDGES) {
        int s = ei[e];
        int d = ei[N_EDGES + e];
        int pos = atomicAdd(&g_cursor[d], 1);
        g_csrc[pos] = s;
    }
}

// ---------------- wb: per-node bias term hn_s . bvec_h ----------------
__global__ void wb_kernel(const float* __restrict__ bvec) {
    int t = blockIdx.x * blockDim.x + threadIdx.x;
    if (t >= N_NODES * NHEADS) return;
    const int node = t >> 2, hh = t & 3;
    const float* bv = bvec + hh * 128;
    float s = 0.f;
    #pragma unroll 8
    for (int j = 0; j < 32; j++) {
        const float4 a = h4_to_f4(*(const uint2*)(g_ah + (size_t)node * 128 + j * 4));
        const float4 w = *(const float4*)(bv + j * 4);
        s += a.x * w.x + a.y * w.y + a.z * w.z + a.w * w.w;
    }
    g_wb[t] = s;
}

// ---------------- attention: warp per node, accumulate u_h = sum a_h * hn_s ----------------
__global__ void __launch_bounds__(128) attn_u_kernel() {
    const int warp = threadIdx.x >> 5, lane = threadIdx.x & 31;
    const int node = blockIdx.x * 4 + warp;
    if (node >= N_NODES) return;
    const int beg = g_indptr[node], end = g_indptr[node + 1];
    float4 qe[4];
    #pragma unroll
    for (int hh = 0; hh < 4; hh++)
        qe[hh] = h4_to_f4(*(const uint2*)(g_kvh + (size_t)node * QEDIM + hh * 128 + lane * 4));
    float ss0 = 0.f, ss1 = 0.f, ss2 = 0.f, ss3 = 0.f;
    float4 u0 = {0,0,0,0}, u1 = {0,0,0,0}, u2 = {0,0,0,0}, u3 = {0,0,0,0};
    int i = beg;
    for (; i + 2 <= end; i += 2) {
        const int s0 = g_csrc[i], s1 = g_csrc[i + 1];
        const float4 f0 = h4_to_f4(*(const uint2*)(g_ah + (size_t)s0 * 128 + lane * 4));
        const float4 f1 = h4_to_f4(*(const uint2*)(g_ah + (size_t)s1 * 128 + lane * 4));
        const float4 wb0 = *(const float4*)&g_wb[s0 * 4];
        const float4 wb1 = *(const float4*)&g_wb[s1 * 4];
        float d00 = qe[0].x*f0.x + qe[0].y*f0.y + qe[0].z*f0.z + qe[0].w*f0.w;
        float d01 = qe[1].x*f0.x + qe[1].y*f0.y + qe[1].z*f0.z + qe[1].w*f0.w;
        float d02 = qe[2].x*f0.x + qe[2].y*f0.y + qe[2].z*f0.z + qe[2].w*f0.w;
        float d03 = qe[3].x*f0.x + qe[3].y*f0.y + qe[3].z*f0.z + qe[3].w*f0.w;
        float d10 = qe[0].x*f1.x + qe[0].y*f1.y + qe[0].z*f1.z + qe[0].w*f1.w;
        float d11 = qe[1].x*f1.x + qe[1].y*f1.y + qe[1].z*f1.z + qe[1].w*f1.w;
        float d12 = qe[2].x*f1.x + qe[2].y*f1.y + qe[2].z*f1.z + qe[2].w*f1.w;
        float d13 = qe[3].x*f1.x + qe[3].y*f1.y + qe[3].z*f1.z + qe[3].w*f1.w;
        d00 = warp_sum(d00); d01 = warp_sum(d01);
        d02 = warp_sum(d02); d03 = warp_sum(d03);
        d10 = warp_sum(d10); d11 = warp_sum(d11);
        d12 = warp_sum(d12); d13 = warp_sum(d13);
        const float p00 = __expf(d00 + wb0.x), p01 = __expf(d01 + wb0.y);
        const float p02 = __expf(d02 + wb0.z), p03 = __expf(d03 + wb0.w);
        const float p10 = __expf(d10 + wb1.x), p11 = __expf(d11 + wb1.y);
        const float p12 = __expf(d12 + wb1.z), p13 = __expf(d13 + wb1.w);
        ss0 += p00 + p10; ss1 += p01 + p11;
        ss2 += p02 + p12; ss3 += p03 + p13;
        u0.x += p00*f0.x + p10*f1.x; u0.y += p00*f0.y + p10*f1.y;
        u0.z += p00*f0.z + p10*f1.z; u0.w += p00*f0.w + p10*f1.w;
        u1.x += p01*f0.x + p11*f1.x; u1.y += p01*f0.y + p11*f1.y;
        u1.z += p01*f0.z + p11*f1.z; u1.w += p01*f0.w + p11*f1.w;
        u2.x += p02*f0.x + p12*f1.x; u2.y += p02*f0.y + p12*f1.y;
        u2.z += p02*f0.z + p12*f1.z; u2.w += p02*f0.w + p12*f1.w;
        u3.x += p03*f0.x + p13*f1.x; u3.y += p03*f0.y + p13*f1.y;
        u3.z += p03*f0.z + p13*f1.z; u3.w += p03*f0.w + p13*f1.w;
    }
    for (; i < end; i++) {
        const int s0 = g_csrc[i];
        const float4 f0 = h4_to_f4(*(const uint2*)(g_ah + (size_t)s0 * 128 + lane * 4));
        const float4 wb0 = *(const float4*)&g_wb[s0 * 4];
        float d00 = qe[0].x*f0.x + qe[0].y*f0.y + qe[0].z*f0.z + qe[0].w*f0.w;
        float d01 = qe[1].x*f0.x + qe[1].y*f0.y + qe[1].z*f0.z + qe[1].w*f0.w;
        float d02 = qe[2].x*f0.x + qe[2].y*f0.y + qe[2].z*f0.z + qe[2].w*f0.w;
        float d03 = qe[3].x*f0.x + qe[3].y*f0.y + qe[3].z*f0.z + qe[3].w*f0.w;
        d00 = warp_sum(d00); d01 = warp_sum(d01);
        d02 = warp_sum(d02); d03 = warp_sum(d03);
        const float p00 = __expf(d00 + wb0.x), p01 = __expf(d01 + wb0.y);
        const float p02 = __expf(d02 + wb0.z), p03 = __expf(d03 + wb0.w);
        ss0 += p00; ss1 += p01; ss2 += p02; ss3 += p03;
        u0.x += p00*f0.x; u0.y += p00*f0.y; u0.z += p00*f0.z; u0.w += p00*f0.w;
        u1.x += p01*f0.x; u1.y += p01*f0.y; u1.z += p01*f0.z; u1.w += p01*f0.w;
        u2.x += p02*f0.x; u2.y += p02*f0.y; u2.z += p02*f0.z; u2.w += p02*f0.w;
        u3.x += p03*f0.x; u3.y += p03*f0.y; u3.z += p03*f0.z; u3.w += p03*f0.w;
    }
    const float i0 = ss0 > 0.f ? 1.f / ss0 : 0.f;
    const float i1 = ss1 > 0.f ? 1.f / ss1 : 0.f;
    const float i2 = ss2 > 0.f ? 1.f / ss2 : 0.f;
    const float i3 = ss3 > 0.f ? 1.f / ss3 : 0.f;
    __half* up = g_mh + (size_t)node * 512 + lane * 4;
    uint2 o0, o1, o2, o3;
    *(__half2*)&o0.x = __floats2half2_rn(u0.x * i0, u0.y * i0);
    *(__half2*)&o0.y = __floats2half2_rn(u0.z * i0, u0.w * i0);
    *(__half2*)&o1.x = __floats2half2_rn(u1.x * i1, u1.y * i1);
    *(__half2*)&o1.y = __floats2half2_rn(u1.z * i1, u1.w * i1);
    *(__half2*)&o2.x = __floats2half2_rn(u2.x * i2, u2.y * i2);
    *(__half2*)&o2.y = __floats2half2_rn(u2.z * i2, u2.w * i2);
    *(__half2*)&o3.x = __floats2half2_rn(u3.x * i3, u3.y * i3);
    *(__half2*)&o3.y = __floats2half2_rn(u3.z * i3, u3.w * i3);
    *(uint2*)(up)       = o0;
    *(uint2*)(up + 128) = o1;
    *(uint2*)(up + 256) = o2;
    *(uint2*)(up + 384) = o3;
}

// ---------------- fp16 HMMA GEMM, cp.async 2-stage, K-chunk 64 ----------------
// 256 threads, 8 warps (4 row x 2 col groups), warp tile 32x64, CTA 128x128.
// EPI 1: OutH = fp16(gelu(acc+bias)), direct stores (pitch N)
// EPI 2: C += gs*(acc+bias); LN(C) -> OutF(fp32) or OutH(fp16)   (N==128)
// EPI 3: C  = acc+bias;      LN(C) -> OutH(fp16)                 (N==128)
// EPI 4: col0<512 -> fp16 qeff (pitch 512); col0>=512 -> fp32 xr (pitch 128)
// EPI 5: out=acc+bias; beta gate(Wb via OutF) + residual(C,gs) + LN -> OutH
#define MG_SMEM_BYTES (128 * 132 * 4)

template <int EPI>
__global__ void __launch_bounds__(256, 2) mma_gemm_kernel(
    const __half* __restrict__ A, const __half* __restrict__ Bt,
    const float* __restrict__ bias, float* __restrict__ C,
    const float* __restrict__ gscale,
    __half* __restrict__ OutH, float* __restrict__ OutF,
    const float* __restrict__ lns, const float* __restrict__ lnb,
    float* __restrict__ OutXr,
    int M, int N, int K)
{
    extern __shared__ char smem[];
    float* Cs = (float*)smem;
    const int tid = threadIdx.x;
    const int wid = tid >> 5, lane = tid & 31;
    const int wr = wid & 3, wc = wid >> 2;
    const int row0 = blockIdx.y * 128, col0 = blockIdx.x * 128;
    const uint32_t sb = smem_to_u32(smem);

    float acc[2][8][4];
    #pragma unroll
    for (int a = 0; a < 2; a++)
        #pragma unroll
        for (int b = 0; b < 8; b++)
            #pragma unroll
            for (int c = 0; c < 4; c++) acc[a][b][c] = 0.f;

    const int a_row = (lane & 7) + (((lane >> 3) & 1) << 3);
    const int a_kb  = (lane >> 4) << 3;
    const int b_n   = (lane & 7) + ((lane >> 4) << 3);
    const int b_kb  = ((lane >> 3) & 1) << 3;

    const int nchunks = K >> 6;

    auto stage = [&](int c, int s) {
        const int kc = c << 6;
        const uint32_t abase = sb + s * 32768;
        const uint32_t bbase = abase + 16384;
        #pragma unroll
        for (int i = 0; i < 4; i++) {
            const int idx = i * 256 + tid;
            const int r = idx >> 3, ch = idx & 7;
            const uint32_t sw = SWZ128((uint32_t)(r * 128 + ch * 16));
            {
                const int grow = row0 + r;
                const __half* src = A + (size_t)grow * K + kc + ch * 8;
                cp_async16(abase + sw, src, (grow < M) ? 16 : 0);
            }
            {
                const __half* src = Bt + (size_t)(col0 + r) * K + kc + ch * 8;
                cp_async16(bbase + sw, src, 16);
            }
        }
    };

    stage(0, 0); CP_COMMIT();
    if (nchunks > 1) stage(1, 1);
    CP_COMMIT();

    for (int c = 0; c < nchunks; c++) {
        CP_WAIT1();
        __syncthreads();
        const int s = c & 1;
        const uint32_t abase = sb + s * 32768;
        const uint32_t bbase = abase + 16384;
        #pragma unroll
        for (int ks = 0; ks < 4; ks++) {
            uint32_t ah[2][4];
            #pragma unroll
            for (int mt = 0; mt < 2; mt++) {
                const int rrow = wr * 32 + mt * 16 + a_row;
                const uint32_t off = SWZ128((uint32_t)(rrow * 128 + (ks * 16 + a_kb) * 2));
                ldsm_x4(ah[mt], abase + off);
            }
            #pragma unroll
            for (int nt2 = 0; nt2 < 4; nt2++) {
                uint32_t bh[4];
                const int nrow = wc * 64 + nt2 * 16 + b_n;
                const uint32_t off = SWZ128((uint32_t)(nrow * 128 + (ks * 16 + b_kb) * 2));
                ldsm_x4(bh, bbase + off);
                #pragma unroll
                for (int mt = 0; mt < 2; mt++) {
                    mma16816h(acc[mt][nt2 * 2 + 0], ah[mt], bh);
                    mma16816h(acc[mt][nt2 * 2 + 1], ah[mt], bh + 2);
                }
            }
        }
        __syncthreads();
        if (c + 2 < nchunks) stage(c + 2, s);
        CP_COMMIT();
    }

    if (EPI == 1 || EPI == 4) {
        #pragma unroll
        for (int mt = 0; mt < 2; mt++) {
            const int r0g = row0 + wr * 32 + mt * 16 + (lane >> 2);
            #pragma unroll
            for (int nt = 0; nt < 8; nt++) {
                const int cg = col0 + wc * 64 + nt * 8 + ((lane & 3) << 1);
                const float b0 = __ldg(&bias[cg + 0]);
                const float b1 = __ldg(&bias[cg + 1]);
                float v00 = acc[mt][nt][0] + b0, v01 = acc[mt][nt][1] + b1;
                float v10 = acc[mt][nt][2] + b0, v11 = acc[mt][nt][3] + b1;
                if (EPI == 1) {
                    if (r0g < M)
                        *(__half2*)(OutH + (size_t)r0g * N + cg) =
                            __floats2half2_rn(gelu_f(v00), gelu_f(v01));
                    if (r0g + 8 < M)
                        *(__half2*)(OutH + (size_t)(r0g + 8) * N + cg) =
                            __floats2half2_rn(gelu_f(v10), gelu_f(v11));
                } else {
                    if (col0 >= 512) {
                        const int cl = cg - 512;
                        if (r0g < M)
                            *(float2*)(OutXr + (size_t)r0g * 128 + cl) =
                                make_float2(v00, v01);
                        if (r0g + 8 < M)
                            *(float2*)(OutXr + (size_t)(r0g + 8) * 128 + cl) =
                                make_float2(v10, v11);
                    } else {
                        if (r0g < M)
                            *(__half2*)(OutH + (size_t)r0g * QEDIM + cg) =
                                __floats2half2_rn(v00, v01);
                        if (r0g + 8 < M)
                            *(__half2*)(OutH + (size_t)(r0g + 8) * QEDIM + cg) =
                                __floats2half2_rn(v10, v11);
                    }
                }
            }
        }
    } else {
        #pragma unroll
        for (int mt = 0; mt < 2; mt++)
            #pragma unroll
            for (int nt = 0; nt < 8; nt++)
                #pragma unroll
                for (int i = 0; i < 4; i++) {
                    const int r = wr * 32 + mt * 16 + (lane >> 2) + ((i >> 1) << 3);
                    const int cc = wc * 64 + nt * 8 + ((lane & 3) << 1) + (i & 1);
                    Cs[r * 132 + cc] = acc[mt][nt][i];
                }
        __syncthreads();
        const float4 b4 = *(const float4*)&bias[lane * 4];
        const float4 sv = *(const float4*)&lns[lane * 4];
        const float4 bvv = *(const float4*)&lnb[lane * 4];
        const float gs = (EPI == 2 || EPI == 5) ? *gscale : 0.f;
        float4 w0, w1, w2;
        if (EPI == 5) {
            const float* Wbp = (const float*)OutF;
            w0 = *(const float4*)&Wbp[lane * 4];
            w1 = *(const float4*)&Wbp[128 + lane * 4];
            w2 = *(const float4*)&Wbp[256 + lane * 4];
        }
        #pragma unroll 4
        for (int j = 0; j < 16; j++) {
            const int r = wid * 16 + j;
            const int row = row0 + r;
            if (row >= M) break;
            const float4 a4 = *(const float4*)&Cs[r * 132 + lane * 4];
            float r0 = a4.x + b4.x, r1 = a4.y + b4.y;
            float r2 = a4.z + b4.z, r3 = a4.w + b4.w;
            if (EPI == 2) {
                const float4 h4 = *(const float4*)&C[(size_t)row * 128 + lane * 4];
                r0 = h4.x + gs * r0; r1 = h4.y + gs * r1;
                r2 = h4.z + gs * r2; r3 = h4.w + gs * r3;
            } else if (EPI == 5) {
                const float4 x4 = *(const float4*)&OutXr[(size_t)row * 128 + lane * 4];
                float p = r0 * w0.x + r1 * w0.y + r2 * w0.z + r3 * w0.w
                        + x4.x * w1.x + x4.y * w1.y + x4.z * w1.z + x4.w * w1.w
                        + (r0 - x4.x) * w2.x + (r1 - x4.y) * w2.y
                        + (r2 - x4.z) * w2.z + (r3 - x4.w) * w2.w;
                p = warp_sum(p);
                const float beta = 1.f / (1.f + __expf(-p));
                const float4 h4 = *(const float4*)&C[(size_t)row * 128 + lane * 4];
                r0 = h4.x + gs * (beta * x4.x + (1.f - beta) * r0);
                r1 = h4.y + gs * (beta * x4.y + (1.f - beta) * r1);
                r2 = h4.z + gs * (beta * x4.z + (1.f - beta) * r2);
                r3 = h4.w + gs * (beta * x4.w + (1.f - beta) * r3);
            }
            *(float4*)&C[(size_t)row * 128 + lane * 4] = make_float4(r0, r1, r2, r3);
            float s1 = r0 + r1 + r2 + r3;
            float s2 = r0 * r0 + r1 * r1 + r2 * r2 + r3 * r3;
            s1 = warp_sum(s1);
            s2 = warp_sum(s2);
            const float mean = s1 * (1.f / 128.f);
            const float var = s2 * (1.f / 128.f) - mean * mean;
            const float inv = rsqrtf(var + 1e-5f);
            const float o0 = (r0 - mean) * inv * sv.x + bvv.x;
            const float o1 = (r1 - mean) * inv * sv.y + bvv.y;
            const float o2 = (r2 - mean) * inv * sv.z + bvv.z;
            const float o3 = (r3 - mean) * inv * sv.w + bvv.w;
            if (EPI == 2 && OutF) {
                *(float4*)&OutF[(size_t)row * 128 + lane * 4] = make_float4(o0, o1, o2, o3);
            } else {
                __half2 p01 = __floats2half2_rn(o0, o1);
                __half2 p23 = __floats2half2_rn(o2, o3);
                __half2* ph = (__half2*)(OutH + (size_t)row * 128 + lane * 4);
                ph[0] = p01; ph[1] = p23;
            }
        }
    }
}

// ---------------- host launch ----------------
extern "C" void kernel_launch(void* const* d_in, const int* in_sizes, int n_in,
                              void* d_out, int out_size) {
    (void)in_sizes; (void)n_in; (void)out_size;
    const float* x     = (const float*)d_in[0];
    const int*   ei    = (const int*)d_in[1];
    const float* Win   = (const float*)d_in[2];
    const float* b_in  = (const float*)d_in[3];
    const float* ln1_s = (const float*)d_in[4];
    const float* ln1_b = (const float*)d_in[5];
    const float* Wq    = (const float*)d_in[6];
    const float* bq    = (const float*)d_in[7];
    const float* Wk    = (const float*)d_in[8];
    const float* bk    = (const float*)d_in[9];
    const float* Wv    = (const float*)d_in[10];
    const float* bv    = (const float*)d_in[11];
    const float* Wskip = (const float*)d_in[12];
    const float* bskip = (const float*)d_in[13];
    const float* Wbeta = (const float*)d_in[14];
    const float* ln2_s = (const float*)d_in[15];
    const float* ln2_b = (const float*)d_in[16];
    const float* W1    = (const float*)d_in[17];
    const float* b1    = (const float*)d_in[18];
    const float* W2    = (const float*)d_in[19];
    const float* b2    = (const float*)d_in[20];
    const float* g1    = (const float*)d_in[21];
    const float* g2    = (const float*)d_in[22];
    const float* lno_s = (const float*)d_in[23];
    const float* lno_b = (const float*)d_in[24];
    (void)bk;

    float *h, *xr, *bkvs, *bvec, *vb;
    __half *kvh, *ah, *mh, *xh, *wh;
    cudaGetSymbolAddress((void**)&h,    g_h);
    cudaGetSymbolAddress((void**)&kvh,  g_kvh);
    cudaGetSymbolAddress((void**)&xr,   g_xr);
    cudaGetSymbolAddress((void**)&bkvs, g_bkvs);
    cudaGetSymbolAddress((void**)&bvec, g_bvec);
    cudaGetSymbolAddress((void**)&vb,   g_vb);
    cudaGetSymbolAddress((void**)&ah,   g_ah);
    cudaGetSymbolAddress((void**)&mh,   g_mh);
    cudaGetSymbolAddress((void**)&xh,   g_xh);
    cudaGetSymbolAddress((void**)&wh,   g_wh);

    static bool attr_done = false;
    if (!attr_done) {
        cudaFuncSetAttribute(mma_gemm_kernel<1>, cudaFuncAttributeMaxDynamicSharedMemorySize, MG_SMEM_BYTES);
        cudaFuncSetAttribute(mma_gemm_kernel<2>, cudaFuncAttributeMaxDynamicSharedMemorySize, MG_SMEM_BYTES);
        cudaFuncSetAttribute(mma_gemm_kernel<3>, cudaFuncAttributeMaxDynamicSharedMemorySize, MG_SMEM_BYTES);
        cudaFuncSetAttribute(mma_gemm_kernel<4>, cudaFuncAttributeMaxDynamicSharedMemorySize, MG_SMEM_BYTES);
        cudaFuncSetAttribute(mma_gemm_kernel<5>, cudaFuncAttributeMaxDynamicSharedMemorySize, MG_SMEM_BYTES);
        attr_done = true;
    }

    const int MROWS = (N_NODES + 127) / 128;  // 157

    // [0] G = scale*WqWk^T (+ bvec)
    gmat_kernel<<<(131072 + 1024 + 255) / 256, 256>>>(Wq, Wk, bq);
    // [1] pack fp16 weights + biases + x
    prep_all<<<(PREP_TOTAL + 255) / 256, 256>>>(Wv, Wskip, W1, W2, Win, bv, bskip, x);
    // [2] input projection + LN1(layer0) fused (K=64, 1 chunk)
    mma_gemm_kernel<3><<<dim3(1, MROWS), 256, MG_SMEM_BYTES>>>(
        xh, wh + W_WIN_OFF, b_in, h, nullptr,
        ah, nullptr, ln1_s, ln1_b, nullptr, N_NODES, 128, 64);
    // [3] layer-0 qeff+skip GEMM  (ncu capture slot)
    mma_gemm_kernel<4><<<dim3(5, MROWS), 256, MG_SMEM_BYTES>>>(
        ah, wh, bkvs, nullptr, nullptr,
        kvh, nullptr, nullptr, nullptr, xr, N_NODES, KVS_N, 128);
    // CSR build
    zero_cnt_kernel<<<(N_NODES + 255) / 256, 256>>>();
    deg_kernel<<<(N_EDGES + 255) / 256, 256>>>(ei);
    scan_kernel<<<1, 1024>>>();
    scatter_kernel<<<(N_EDGES + 255) / 256, 256>>>(ei);

    for (int l = 0; l < 2; l++) {
        const int wb = l * W_PER_LAYER;
        if (l == 1) {
            mma_gemm_kernel<4><<<dim3(5, MROWS), 256, MG_SMEM_BYTES>>>(
                ah, wh + wb, bkvs + l * KVS_N, nullptr, nullptr,
                kvh, nullptr, nullptr, nullptr, xr, N_NODES, KVS_N, 128);
        }
        // logit bias term (bq . Wk hn_s) per node/head
        wb_kernel<<<(N_NODES * 4 + 255) / 256, 256>>>(bvec + l * 512);
        // attention: u_h accumulation only (256 B/edge)
        attn_u_kernel<<<(N_NODES + 3) / 4, 128>>>();
        // v-apply GEMM + beta gate + residual + LN2 -> ah
        mma_gemm_kernel<5><<<dim3(1, MROWS), 256, MG_SMEM_BYTES>>>(
            mh, wh + wb + WL_VAPP, vb + l * 128, h, g1 + l,
            ah, (float*)(Wbeta + l * 384), ln2_s + l * 128, ln2_b + l * 128, xr,
            N_NODES, 128, 512);
        // FFN1 (gelu -> fp16 mid)
        mma_gemm_kernel<1><<<dim3(4, MROWS), 256, MG_SMEM_BYTES>>>(
            ah, wh + wb + WL_W1, b1 + l * 512, nullptr, nullptr,
            mh, nullptr, nullptr, nullptr, nullptr, N_NODES, 512, 128);
        // FFN2 + residual + LN (next layer ln1, or final lno -> d_out)
        if (l == 0) {
            mma_gemm_kernel<2><<<dim3(1, MROWS), 256, MG_SMEM_BYTES>>>(
                mh, wh + wb + WL_W2, b2 + l * 128, h, g2 + l,
                ah, nullptr, ln1_s + 128, ln1_b + 128, nullptr,
                N_NODES, 128, 512);
        } else {
            mma_gemm_kernel<2><<<dim3(1, MROWS), 256, MG_SMEM_BYTES>>>(
                mh, wh + wb + WL_W2, b2 + l * 128, h, g2 + l,
                nullptr, (float*)d_out, lno_s, lno_b, nullptr,
                N_NODES, 128, 512);
        }
    }
}

// round 14
// speedup vs baseline: 1.9503x; 1.0782x over previous
#include <cuda_runtime.h>
#include <cuda_bf16.h>
#include <cuda_fp16.h>
#include <math.h>
#include <stdint.h>

#define N_NODES 20000
#define N_EDGES 320000
#define FDIM 32
#define HDIM 128
#define NHEADS 4
#define QEDIM 512     // qeff row (fp16)

// ---------------- device-global scratch ----------------
__device__ float g_h[N_NODES * HDIM];
__device__ __half g_kvh[N_NODES * QEDIM];   // qeff' (includes bvec)
__device__ float g_xr[N_NODES * HDIM];
__device__ int   g_indptr[N_NODES + 1];
__device__ int   g_cnt[N_NODES];
__device__ int   g_cursor[N_NODES];
__device__ int   g_csrc[N_EDGES];
// fp16 activation buffers
__device__ __half g_ah[N_NODES * HDIM];    // hn (LN output)
__device__ __half g_mh[N_NODES * 512];     // u_cat, then FFN mid
__device__ __half g_xh[N_NODES * 64];      // padded input
// G = scale * Wq Wk^T per head + bvec
__device__ float g_G[2 * 512 * 128];
__device__ float g_bvec[2 * 4 * 128];
// packed transposed fp16 weights (per layer):
//  [0,65536)        QEFF  Bt[n=h*128+i][k] = G_h[k][i]
//  [65536,81920)    SKIP  [128][128]
//  [81920,147456)   VAPP  Bt[n=i][k=h*128+j] = 0.25*Wv[j][h*128+i]
//  [147456,212992)  W1    [512][128]
//  [212992,278528)  W2    [128][512]
#define WL_QEFF 0
#define WL_SKIP 65536
#define WL_VAPP 81920
#define WL_W1   147456
#define WL_W2   212992
#define W_PER_LAYER 278528
#define W_WIN_OFF 557056
#define W_TOTAL 565248
#define KVS_N 640
#define PREP_TOTAL (W_TOTAL + 2 * KVS_N + 256 + N_NODES * 64)
__device__ __half g_wh[W_TOTAL];
__device__ float g_bkvs[2 * KVS_N];
__device__ float g_vb[2 * 128];

// ---------------- helpers ----------------
__device__ __forceinline__ uint32_t smem_to_u32(const void* p) {
    uint32_t a;
    asm("{ .reg .u64 t; cvta.to.shared.u64 t, %1; cvt.u32.u64 %0, t; }"
        : "=r"(a) : "l"(p));
    return a;
}
#define SWZ128(bo) ((bo) ^ (((bo) >> 3) & 0x70))

__device__ __forceinline__ void cp_async16(uint32_t dst, const void* src, int szbytes) {
    asm volatile("cp.async.cg.shared.global [%0], [%1], 16, %2;"
        :: "r"(dst), "l"(src), "r"(szbytes));
}
#define CP_COMMIT() asm volatile("cp.async.commit_group;" ::: "memory")
#define CP_WAIT1()  asm volatile("cp.async.wait_group 1;" ::: "memory")

__device__ __forceinline__ void ldsm_x4(uint32_t* r, uint32_t addr) {
    asm volatile("ldmatrix.sync.aligned.m8n8.x4.shared.b16 {%0,%1,%2,%3}, [%4];"
        : "=r"(r[0]), "=r"(r[1]), "=r"(r[2]), "=r"(r[3]) : "r"(addr));
}
__device__ __forceinline__ void mma16816h(float* c, const uint32_t* a, const uint32_t* b) {
    asm volatile("mma.sync.aligned.m16n8k16.row.col.f32.f16.f16.f32 "
        "{%0,%1,%2,%3}, {%4,%5,%6,%7}, {%8,%9}, {%0,%1,%2,%3};"
        : "+f"(c[0]), "+f"(c[1]), "+f"(c[2]), "+f"(c[3])
        : "r"(a[0]), "r"(a[1]), "r"(a[2]), "r"(a[3]), "r"(b[0]), "r"(b[1]));
}
__device__ __forceinline__ float gelu_f(float x) {
    return 0.5f * x * (1.0f + erff(x * 0.70710678118654752f));
}
__device__ __forceinline__ float4 h4_to_f4(uint2 raw) {
    const __half2 h0 = *reinterpret_cast<__half2*>(&raw.x);
    const __half2 h1 = *reinterpret_cast<__half2*>(&raw.y);
    const float2 a = __half22float2(h0);
    const float2 b = __half22float2(h1);
    return make_float4(a.x, a.y, b.x, b.y);
}
__device__ __forceinline__ float warp_sum(float v) {
    #pragma unroll
    for (int off = 16; off > 0; off >>= 1)
        v += __shfl_xor_sync(0xffffffffu, v, off);
    return v;
}

// ---------------- G precompute: G_h = scale*Wq_h Wk_h^T, bvec ----------------
__global__ void gmat_kernel(const float* __restrict__ Wq,
                            const float* __restrict__ Wk,
                            const float* __restrict__ bq)
{
    const float scale = 0.08838834764831845f;
    int idx = blockIdx.x * blockDim.x + threadIdx.x;
    if (idx < 131072) {
        const int l = idx >> 16, r = idx & 65535;
        const int n = r >> 7, k = r & 127;
        const int hh = n >> 7, i = n & 127;
        const float4* wq = (const float4*)(Wq + l * 65536 + i * 512 + hh * 128);
        const float4* wk = (const float4*)(Wk + l * 65536 + k * 512 + hh * 128);
        float s = 0.f;
        #pragma unroll 8
        for (int a = 0; a < 32; a++) {
            const float4 qa = __ldg(&wq[a]);
            const float4 ka = __ldg(&wk[a]);
            s += qa.x * ka.x + qa.y * ka.y + qa.z * ka.z + qa.w * ka.w;
        }
        g_G[idx] = s * scale;   // G_h[i][k]
    } else if (idx < 131072 + 1024) {
        const int r = idx - 131072;
        const int l = r >> 9, r2 = r & 511;
        const int hh = r2 >> 7, j = r2 & 127;
        const float* b = bq + l * 512 + hh * 128;
        const float* wk = Wk + l * 65536 + j * 512 + hh * 128;
        float s = 0.f;
        for (int a = 0; a < 128; a++) s += __ldg(&b[a]) * __ldg(&wk[a]);
        g_bvec[r] = s * scale;
    }
}

// ---------------- one-shot packer: fp16 weights + biases + x ----------------
__global__ void prep_all(
    const float* __restrict__ Wv, const float* __restrict__ Wskip,
    const float* __restrict__ W1, const float* __restrict__ W2,
    const float* __restrict__ Win,
    const float* __restrict__ bv, const float* __restrict__ bskip,
    const float* __restrict__ x)
{
    int idx = blockIdx.x * blockDim.x + threadIdx.x;
    if (idx >= PREP_TOTAL) return;
    if (idx >= W_TOTAL + 2 * KVS_N + 256) {
        const int r = idx - (W_TOTAL + 2 * KVS_N + 256);
        const int row = r >> 6, k = r & 63;
        const float val = (k < 32) ? __ldg(&x[row * 32 + k]) : 0.f;
        g_xh[r] = __float2half_rn(val);
        return;
    }
    if (idx >= W_TOTAL + 2 * KVS_N) {
        const int r = idx - (W_TOTAL + 2 * KVS_N);
        const int l = r >> 7, ii = r & 127;
        const float* b = bv + l * 512;
        g_vb[r] = 0.25f * (__ldg(&b[ii]) + __ldg(&b[128 + ii]) +
                           __ldg(&b[256 + ii]) + __ldg(&b[384 + ii]));
        return;
    }
    if (idx >= W_TOTAL) {
        const int r = idx - W_TOTAL;
        const int l = r / KVS_N, c = r % KVS_N;
        // qeff columns get the folded bvec bias; skip columns get bskip
        g_bkvs[r] = (c < 512) ? g_bvec[l * 512 + c]
                              : __ldg(&bskip[l * 128 + c - 512]);
        return;
    }
    float val;
    if (idx < W_WIN_OFF) {
        const int l = idx / W_PER_LAYER, r = idx % W_PER_LAYER;
        if (r < WL_SKIP) {
            const int n = r / 128, k = r % 128;
            const int hh = n >> 7, i = n & 127;
            val = g_G[l * 65536 + (hh * 128 + k) * 128 + i];   // G_h[k][i]
        } else if (r < WL_VAPP) {
            const int r2 = r - WL_SKIP, n = r2 / 128, k = r2 % 128;
            val = __ldg(&Wskip[l * 16384 + k * 128 + n]);
        } else if (r < WL_W1) {
            const int r3 = r - WL_VAPP, n = r3 / 512, k = r3 % 512;
            const int hh = k >> 7, j = k & 127;
            val = 0.25f * __ldg(&Wv[l * 65536 + j * 512 + hh * 128 + n]);
        } else if (r < WL_W2) {
            const int r4 = r - WL_W1, n = r4 / 128, k = r4 % 128;
            val = __ldg(&W1[l * 65536 + k * 512 + n]);
        } else {
            const int r5 = r - WL_W2, n = r5 / 512, k = r5 % 512;
            val = __ldg(&W2[l * 65536 + k * 128 + n]);
        }
    } else {
        const int r6 = idx - W_WIN_OFF, n = r6 / 64, k = r6 % 64;
        val = (k < 32) ? __ldg(&Win[k * 128 + n]) : 0.f;
    }
    g_wh[idx] = __float2half_rn(val);
}

// ---------------- CSR build ----------------
__global__ void zero_cnt_kernel() {
    int i = blockIdx.x * blockDim.x + threadIdx.x;
    if (i < N_NODES) g_cnt[i] = 0;
}
__global__ void deg_kernel(const int* __restrict__ ei) {
    int e = blockIdx.x * blockDim.x + threadIdx.x;
    if (e < N_EDGES) atomicAdd(&g_cnt[ei[N_EDGES + e]], 1);
}
__global__ void scan_kernel() {
    __shared__ int wsum[32];
    __shared__ int carry;
    const int tid = threadIdx.x, lane = tid & 31, wid = tid >> 5;
    if (tid == 0) { carry = 0; g_indptr[0] = 0; }
    __syncthreads();
    for (int base = 0; base < N_NODES; base += 1024) {
        int i = base + tid;
        int v = (i < N_NODES) ? g_cnt[i] : 0;
        int x = v;
        #pragma unroll
        for (int off = 1; off < 32; off <<= 1) {
            int y = __shfl_up_sync(0xffffffffu, x, off);
            if (lane >= off) x += y;
        }
        if (lane == 31) wsum[wid] = x;
        __syncthreads();
        if (wid == 0) {
            int w = wsum[lane];
            #pragma unroll
            for (int off = 1; off < 32; off <<= 1) {
                int y = __shfl_up_sync(0xffffffffu, w, off);
                if (lane >= off) w += y;
            }
            wsum[lane] = w;
        }
        __syncthreads();
        int incl = carry + (wid > 0 ? wsum[wid - 1] : 0) + x;
        if (i < N_NODES) {
            g_indptr[i + 1] = incl;
            g_cursor[i] = incl - v;
        }
        __syncthreads();
        if (tid == 1023) carry = incl;
        __syncthreads();
    }
}
__global__ void scatter_kernel(const int* __restrict__ ei) {
    int e = blockIdx.x * blockDim.x + threadIdx.x;
    if (e < N_EDGES) {
        int s = ei[e];
        int d = ei[N_EDGES + e];
        int pos = atomicAdd(&g_cursor[d], 1);
        g_csrc[pos] = s;
    }
}

// ---------------- attention: warp per node, u_h = sum a_h * hn_s ----------------
__global__ void __launch_bounds__(128) attn_u_kernel() {
    const int warp = threadIdx.x >> 5, lane = threadIdx.x & 31;
    const int node = blockIdx.x * 4 + warp;
    if (node >= N_NODES) return;
    const int beg = g_indptr[node], end = g_indptr[node + 1];
    float4 qe[4];
    #pragma unroll
    for (int hh = 0; hh < 4; hh++)
        qe[hh] = h4_to_f4(*(const uint2*)(g_kvh + (size_t)node * QEDIM + hh * 128 + lane * 4));
    float ss0 = 0.f, ss1 = 0.f, ss2 = 0.f, ss3 = 0.f;
    float4 u0 = {0,0,0,0}, u1 = {0,0,0,0}, u2 = {0,0,0,0}, u3 = {0,0,0,0};
    int i = beg;
    for (; i + 4 <= end; i += 4) {
        const int s0 = g_csrc[i], s1 = g_csrc[i + 1];
        const int s2 = g_csrc[i + 2], s3 = g_csrc[i + 3];
        const float4 f0 = h4_to_f4(*(const uint2*)(g_ah + (size_t)s0 * 128 + lane * 4));
        const float4 f1 = h4_to_f4(*(const uint2*)(g_ah + (size_t)s1 * 128 + lane * 4));
        const float4 f2 = h4_to_f4(*(const uint2*)(g_ah + (size_t)s2 * 128 + lane * 4));
        const float4 f3 = h4_to_f4(*(const uint2*)(g_ah + (size_t)s3 * 128 + lane * 4));
        float d00 = qe[0].x*f0.x + qe[0].y*f0.y + qe[0].z*f0.z + qe[0].w*f0.w;
        float d01 = qe[1].x*f0.x + qe[1].y*f0.y + qe[1].z*f0.z + qe[1].w*f0.w;
        float d02 = qe[2].x*f0.x + qe[2].y*f0.y + qe[2].z*f0.z + qe[2].w*f0.w;
        float d03 = qe[3].x*f0.x + qe[3].y*f0.y + qe[3].z*f0.z + qe[3].w*f0.w;
        float d10 = qe[0].x*f1.x + qe[0].y*f1.y + qe[0].z*f1.z + qe[0].w*f1.w;
        float d11 = qe[1].x*f1.x + qe[1].y*f1.y + qe[1].z*f1.z + qe[1].w*f1.w;
        float d12 = qe[2].x*f1.x + qe[2].y*f1.y + qe[2].z*f1.z + qe[2].w*f1.w;
        float d13 = qe[3].x*f1.x + qe[3].y*f1.y + qe[3].z*f1.z + qe[3].w*f1.w;
        float d20 = qe[0].x*f2.x + qe[0].y*f2.y + qe[0].z*f2.z + qe[0].w*f2.w;
        float d21 = qe[1].x*f2.x + qe[1].y*f2.y + qe[1].z*f2.z + qe[1].w*f2.w;
        float d22 = qe[2].x*f2.x + qe[2].y*f2.y + qe[2].z*f2.z + qe[2].w*f2.w;
        float d23 = qe[3].x*f2.x + qe[3].y*f2.y + qe[3].z*f2.z + qe[3].w*f2.w;
        float d30 = qe[0].x*f3.x + qe[0].y*f3.y + qe[0].z*f3.z + qe[0].w*f3.w;
        float d31 = qe[1].x*f3.x + qe[1].y*f3.y + qe[1].z*f3.z + qe[1].w*f3.w;
        float d32 = qe[2].x*f3.x + qe[2].y*f3.y + qe[2].z*f3.z + qe[2].w*f3.w;
        float d33 = qe[3].x*f3.x + qe[3].y*f3.y + qe[3].z*f3.z + qe[3].w*f3.w;
        d00 = warp_sum(d00); d01 = warp_sum(d01);
        d02 = warp_sum(d02); d03 = warp_sum(d03);
        d10 = warp_sum(d10); d11 = warp_sum(d11);
        d12 = warp_sum(d12); d13 = warp_sum(d13);
        d20 = warp_sum(d20); d21 = warp_sum(d21);
        d22 = warp_sum(d22); d23 = warp_sum(d23);
        d30 = warp_sum(d30); d31 = warp_sum(d31);
        d32 = warp_sum(d32); d33 = warp_sum(d33);
        const float p00 = __expf(d00), p01 = __expf(d01);
        const float p02 = __expf(d02), p03 = __expf(d03);
        const float p10 = __expf(d10), p11 = __expf(d11);
        const float p12 = __expf(d12), p13 = __expf(d13);
        const float p20 = __expf(d20), p21 = __expf(d21);
        const float p22 = __expf(d22), p23 = __expf(d23);
        const float p30 = __expf(d30), p31 = __expf(d31);
        const float p32 = __expf(d32), p33 = __expf(d33);
        ss0 += (p00 + p10) + (p20 + p30);
        ss1 += (p01 + p11) + (p21 + p31);
        ss2 += (p02 + p12) + (p22 + p32);
        ss3 += (p03 + p13) + (p23 + p33);
        u0.x += p00*f0.x + p10*f1.x + p20*f2.x + p30*f3.x;
        u0.y += p00*f0.y + p10*f1.y + p20*f2.y + p30*f3.y;
        u0.z += p00*f0.z + p10*f1.z + p20*f2.z + p30*f3.z;
        u0.w += p00*f0.w + p10*f1.w + p20*f2.w + p30*f3.w;
        u1.x += p01*f0.x + p11*f1.x + p21*f2.x + p31*f3.x;
        u1.y += p01*f0.y + p11*f1.y + p21*f2.y + p31*f3.y;
        u1.z += p01*f0.z + p11*f1.z + p21*f2.z + p31*f3.z;
        u1.w += p01*f0.w + p11*f1.w + p21*f2.w + p31*f3.w;
        u2.x += p02*f0.x + p12*f1.x + p22*f2.x + p32*f3.x;
        u2.y += p02*f0.y + p12*f1.y + p22*f2.y + p32*f3.y;
        u2.z += p02*f0.z + p12*f1.z + p22*f2.z + p32*f3.z;
        u2.w += p02*f0.w + p12*f1.w + p22*f2.w + p32*f3.w;
        u3.x += p03*f0.x + p13*f1.x + p23*f2.x + p33*f3.x;
        u3.y += p03*f0.y + p13*f1.y + p23*f2.y + p33*f3.y;
        u3.z += p03*f0.z + p13*f1.z + p23*f2.z + p33*f3.z;
        u3.w += p03*f0.w + p13*f1.w + p23*f2.w + p33*f3.w;
    }
    for (; i < end; i++) {
        const int s0 = g_csrc[i];
        const float4 f0 = h4_to_f4(*(const uint2*)(g_ah + (size_t)s0 * 128 + lane * 4));
        float d00 = qe[0].x*f0.x + qe[0].y*f0.y + qe[0].z*f0.z + qe[0].w*f0.w;
        float d01 = qe[1].x*f0.x + qe[1].y*f0.y + qe[1].z*f0.z + qe[1].w*f0.w;
        float d02 = qe[2].x*f0.x + qe[2].y*f0.y + qe[2].z*f0.z + qe[2].w*f0.w;
        float d03 = qe[3].x*f0.x + qe[3].y*f0.y + qe[3].z*f0.z + qe[3].w*f0.w;
        d00 = warp_sum(d00); d01 = warp_sum(d01);
        d02 = warp_sum(d02); d03 = warp_sum(d03);
        const float p00 = __expf(d00), p01 = __expf(d01);
        const float p02 = __expf(d02), p03 = __expf(d03);
        ss0 += p00; ss1 += p01; ss2 += p02; ss3 += p03;
        u0.x += p00*f0.x; u0.y += p00*f0.y; u0.z += p00*f0.z; u0.w += p00*f0.w;
        u1.x += p01*f0.x; u1.y += p01*f0.y; u1.z += p01*f0.z; u1.w += p01*f0.w;
        u2.x += p02*f0.x; u2.y += p02*f0.y; u2.z += p02*f0.z; u2.w += p02*f0.w;
        u3.x += p03*f0.x; u3.y += p03*f0.y; u3.z += p03*f0.z; u3.w += p03*f0.w;
    }
    const float i0 = ss0 > 0.f ? 1.f / ss0 : 0.f;
    const float i1 = ss1 > 0.f ? 1.f / ss1 : 0.f;
    const float i2 = ss2 > 0.f ? 1.f / ss2 : 0.f;
    const float i3 = ss3 > 0.f ? 1.f / ss3 : 0.f;
    __half* up = g_mh + (size_t)node * 512 + lane * 4;
    uint2 o0, o1, o2, o3;
    *(__half2*)&o0.x = __floats2half2_rn(u0.x * i0, u0.y * i0);
    *(__half2*)&o0.y = __floats2half2_rn(u0.z * i0, u0.w * i0);
    *(__half2*)&o1.x = __floats2half2_rn(u1.x * i1, u1.y * i1);
    *(__half2*)&o1.y = __floats2half2_rn(u1.z * i1, u1.w * i1);
    *(__half2*)&o2.x = __floats2half2_rn(u2.x * i2, u2.y * i2);
    *(__half2*)&o2.y = __floats2half2_rn(u2.z * i2, u2.w * i2);
    *(__half2*)&o3.x = __floats2half2_rn(u3.x * i3, u3.y * i3);
    *(__half2*)&o3.y = __floats2half2_rn(u3.z * i3, u3.w * i3);
    *(uint2*)(up)       = o0;
    *(uint2*)(up + 128) = o1;
    *(uint2*)(up + 256) = o2;
    *(uint2*)(up + 384) = o3;
}

// ---------------- fp16 HMMA GEMM, cp.async 2-stage, K-chunk 64 ----------------
// EPI 1: OutH = fp16(gelu(acc+bias)), direct stores (pitch N)
// EPI 2: C += gs*(acc+bias); LN(C) -> OutF(fp32) or OutH(fp16)   (N==128)
// EPI 3: C  = acc+bias;      LN(C) -> OutH(fp16)                 (N==128)
// EPI 4: col0<512 -> fp16 qeff (pitch 512); col0>=512 -> fp32 xr (pitch 128)
// EPI 5: out=acc+bias; beta gate(Wb via OutF) + residual(C,gs) + LN -> OutH
#define MG_SMEM_BYTES (128 * 132 * 4)

template <int EPI>
__global__ void __launch_bounds__(256, 2) mma_gemm_kernel(
    const __half* __restrict__ A, const __half* __restrict__ Bt,
    const float* __restrict__ bias, float* __restrict__ C,
    const float* __restrict__ gscale,
    __half* __restrict__ OutH, float* __restrict__ OutF,
    const float* __restrict__ lns, const float* __restrict__ lnb,
    float* __restrict__ OutXr,
    int M, int N, int K)
{
    extern __shared__ char smem[];
    float* Cs = (float*)smem;
    const int tid = threadIdx.x;
    const int wid = tid >> 5, lane = tid & 31;
    const int wr = wid & 3, wc = wid >> 2;
    const int row0 = blockIdx.y * 128, col0 = blockIdx.x * 128;
    const uint32_t sb = smem_to_u32(smem);

    float acc[2][8][4];
    #pragma unroll
    for (int a = 0; a < 2; a++)
        #pragma unroll
        for (int b = 0; b < 8; b++)
            #pragma unroll
            for (int c = 0; c < 4; c++) acc[a][b][c] = 0.f;

    const int a_row = (lane & 7) + (((lane >> 3) & 1) << 3);
    const int a_kb  = (lane >> 4) << 3;
    const int b_n   = (lane & 7) + ((lane >> 4) << 3);
    const int b_kb  = ((lane >> 3) & 1) << 3;

    const int nchunks = K >> 6;

    auto stage = [&](int c, int s) {
        const int kc = c << 6;
        const uint32_t abase = sb + s * 32768;
        const uint32_t bbase = abase + 16384;
        #pragma unroll
        for (int i = 0; i < 4; i++) {
            const int idx = i * 256 + tid;
            const int r = idx >> 3, ch = idx & 7;
            const uint32_t sw = SWZ128((uint32_t)(r * 128 + ch * 16));
            {
                const int grow = row0 + r;
                const __half* src = A + (size_t)grow * K + kc + ch * 8;
                cp_async16(abase + sw, src, (grow < M) ? 16 : 0);
            }
            {
                const __half* src = Bt + (size_t)(col0 + r) * K + kc + ch * 8;
                cp_async16(bbase + sw, src, 16);
            }
        }
    };

    stage(0, 0); CP_COMMIT();
    if (nchunks > 1) stage(1, 1);
    CP_COMMIT();

    for (int c = 0; c < nchunks; c++) {
        CP_WAIT1();
        __syncthreads();
        const int s = c & 1;
        const uint32_t abase = sb + s * 32768;
        const uint32_t bbase = abase + 16384;
        #pragma unroll
        for (int ks = 0; ks < 4; ks++) {
            uint32_t ah[2][4];
            #pragma unroll
            for (int mt = 0; mt < 2; mt++) {
                const int rrow = wr * 32 + mt * 16 + a_row;
                const uint32_t off = SWZ128((uint32_t)(rrow * 128 + (ks * 16 + a_kb) * 2));
                ldsm_x4(ah[mt], abase + off);
            }
            #pragma unroll
            for (int nt2 = 0; nt2 < 4; nt2++) {
                uint32_t bh[4];
                const int nrow = wc * 64 + nt2 * 16 + b_n;
                const uint32_t off = SWZ128((uint32_t)(nrow * 128 + (ks * 16 + b_kb) * 2));
                ldsm_x4(bh, bbase + off);
                #pragma unroll
                for (int mt = 0; mt < 2; mt++) {
                    mma16816h(acc[mt][nt2 * 2 + 0], ah[mt], bh);
                    mma16816h(acc[mt][nt2 * 2 + 1], ah[mt], bh + 2);
                }
            }
        }
        __syncthreads();
        if (c + 2 < nchunks) stage(c + 2, s);
        CP_COMMIT();
    }

    if (EPI == 1 || EPI == 4) {
        #pragma unroll
        for (int mt = 0; mt < 2; mt++) {
            const int r0g = row0 + wr * 32 + mt * 16 + (lane >> 2);
            #pragma unroll
            for (int nt = 0; nt < 8; nt++) {
                const int cg = col0 + wc * 64 + nt * 8 + ((lane & 3) << 1);
                const float b0 = __ldg(&bias[cg + 0]);
                const float b1 = __ldg(&bias[cg + 1]);
                float v00 = acc[mt][nt][0] + b0, v01 = acc[mt][nt][1] + b1;
                float v10 = acc[mt][nt][2] + b0, v11 = acc[mt][nt][3] + b1;
                if (EPI == 1) {
                    if (r0g < M)
                        *(__half2*)(OutH + (size_t)r0g * N + cg) =
                            __floats2half2_rn(gelu_f(v00), gelu_f(v01));
                    if (r0g + 8 < M)
                        *(__half2*)(OutH + (size_t)(r0g + 8) * N + cg) =
                            __floats2half2_rn(gelu_f(v10), gelu_f(v11));
                } else {
                    if (col0 >= 512) {
                        const int cl = cg - 512;
                        if (r0g < M)
                            *(float2*)(OutXr + (size_t)r0g * 128 + cl) =
                                make_float2(v00, v01);
                        if (r0g + 8 < M)
                            *(float2*)(OutXr + (size_t)(r0g + 8) * 128 + cl) =
                                make_float2(v10, v11);
                    } else {
                        if (r0g < M)
                            *(__half2*)(OutH + (size_t)r0g * QEDIM + cg) =
                                __floats2half2_rn(v00, v01);
                        if (r0g + 8 < M)
                            *(__half2*)(OutH + (size_t)(r0g + 8) * QEDIM + cg) =
                                __floats2half2_rn(v10, v11);
                    }
                }
            }
        }
    } else {
        #pragma unroll
        for (int mt = 0; mt < 2; mt++)
            #pragma unroll
            for (int nt = 0; nt < 8; nt++)
                #pragma unroll
                for (int i = 0; i < 4; i++) {
                    const int r = wr * 32 + mt * 16 + (lane >> 2) + ((i >> 1) << 3);
                    const int cc = wc * 64 + nt * 8 + ((lane & 3) << 1) + (i & 1);
                    Cs[r * 132 + cc] = acc[mt][nt][i];
                }
        __syncthreads();
        const float4 b4 = *(const float4*)&bias[lane * 4];
        const float4 sv = *(const float4*)&lns[lane * 4];
        const float4 bvv = *(const float4*)&lnb[lane * 4];
        const float gs = (EPI == 2 || EPI == 5) ? *gscale : 0.f;
        float4 w0, w1, w2;
        if (EPI == 5) {
            const float* Wbp = (const float*)OutF;
            w0 = *(const float4*)&Wbp[lane * 4];
            w1 = *(const float4*)&Wbp[128 + lane * 4];
            w2 = *(const float4*)&Wbp[256 + lane * 4];
        }
        #pragma unroll 4
        for (int j = 0; j < 16; j++) {
            const int r = wid * 16 + j;
            const int row = row0 + r;
            if (row >= M) break;
            const float4 a4 = *(const float4*)&Cs[r * 132 + lane * 4];
            float r0 = a4.x + b4.x, r1 = a4.y + b4.y;
            float r2 = a4.z + b4.z, r3 = a4.w + b4.w;
            if (EPI == 2) {
                const float4 h4 = *(const float4*)&C[(size_t)row * 128 + lane * 4];
                r0 = h4.x + gs * r0; r1 = h4.y + gs * r1;
                r2 = h4.z + gs * r2; r3 = h4.w + gs * r3;
            } else if (EPI == 5) {
                const float4 x4 = *(const float4*)&OutXr[(size_t)row * 128 + lane * 4];
                float p = r0 * w0.x + r1 * w0.y + r2 * w0.z + r3 * w0.w
                        + x4.x * w1.x + x4.y * w1.y + x4.z * w1.z + x4.w * w1.w
                        + (r0 - x4.x) * w2.x + (r1 - x4.y) * w2.y
                        + (r2 - x4.z) * w2.z + (r3 - x4.w) * w2.w;
                p = warp_sum(p);
                const float beta = 1.f / (1.f + __expf(-p));
                const float4 h4 = *(const float4*)&C[(size_t)row * 128 + lane * 4];
                r0 = h4.x + gs * (beta * x4.x + (1.f - beta) * r0);
                r1 = h4.y + gs * (beta * x4.y + (1.f - beta) * r1);
                r2 = h4.z + gs * (beta * x4.z + (1.f - beta) * r2);
                r3 = h4.w + gs * (beta * x4.w + (1.f - beta) * r3);
            }
            *(float4*)&C[(size_t)row * 128 + lane * 4] = make_float4(r0, r1, r2, r3);
            float s1 = r0 + r1 + r2 + r3;
            float s2 = r0 * r0 + r1 * r1 + r2 * r2 + r3 * r3;
            s1 = warp_sum(s1);
            s2 = warp_sum(s2);
            const float mean = s1 * (1.f / 128.f);
            const float var = s2 * (1.f / 128.f) - mean * mean;
            const float inv = rsqrtf(var + 1e-5f);
            const float o0 = (r0 - mean) * inv * sv.x + bvv.x;
            const float o1 = (r1 - mean) * inv * sv.y + bvv.y;
            const float o2 = (r2 - mean) * inv * sv.z + bvv.z;
            const float o3 = (r3 - mean) * inv * sv.w + bvv.w;
            if (EPI == 2 && OutF) {
                *(float4*)&OutF[(size_t)row * 128 + lane * 4] = make_float4(o0, o1, o2, o3);
            } else {
                __half2 p01 = __floats2half2_rn(o0, o1);
                __half2 p23 = __floats2half2_rn(o2, o3);
                __half2* ph = (__half2*)(OutH + (size_t)row * 128 + lane * 4);
                ph[0] = p01; ph[1] = p23;
            }
        }
    }
}

// ---------------- host launch ----------------
extern "C" void kernel_launch(void* const* d_in, const int* in_sizes, int n_in,
                              void* d_out, int out_size) {
    (void)in_sizes; (void)n_in; (void)out_size;
    const float* x     = (const float*)d_in[0];
    const int*   ei    = (const int*)d_in[1];
    const float* Win   = (const float*)d_in[2];
    const float* b_in  = (const float*)d_in[3];
    const float* ln1_s = (const float*)d_in[4];
    const float* ln1_b = (const float*)d_in[5];
    const float* Wq    = (const float*)d_in[6];
    const float* bq    = (const float*)d_in[7];
    const float* Wk    = (const float*)d_in[8];
    const float* bk    = (const float*)d_in[9];
    const float* Wv    = (const float*)d_in[10];
    const float* bv    = (const float*)d_in[11];
    const float* Wskip = (const float*)d_in[12];
    const float* bskip = (const float*)d_in[13];
    const float* Wbeta = (const float*)d_in[14];
    const float* ln2_s = (const float*)d_in[15];
    const float* ln2_b = (const float*)d_in[16];
    const float* W1    = (const float*)d_in[17];
    const float* b1    = (const float*)d_in[18];
    const float* W2    = (const float*)d_in[19];
    const float* b2    = (const float*)d_in[20];
    const float* g1    = (const float*)d_in[21];
    const float* g2    = (const float*)d_in[22];
    const float* lno_s = (const float*)d_in[23];
    const float* lno_b = (const float*)d_in[24];
    (void)bk;

    float *h, *xr, *bkvs, *vb;
    __half *kvh, *ah, *mh, *xh, *wh;
    cudaGetSymbolAddress((void**)&h,    g_h);
    cudaGetSymbolAddress((void**)&kvh,  g_kvh);
    cudaGetSymbolAddress((void**)&xr,   g_xr);
    cudaGetSymbolAddress((void**)&bkvs, g_bkvs);
    cudaGetSymbolAddress((void**)&vb,   g_vb);
    cudaGetSymbolAddress((void**)&ah,   g_ah);
    cudaGetSymbolAddress((void**)&mh,   g_mh);
    cudaGetSymbolAddress((void**)&xh,   g_xh);
    cudaGetSymbolAddress((void**)&wh,   g_wh);

    static bool attr_done = false;
    if (!attr_done) {
        cudaFuncSetAttribute(mma_gemm_kernel<1>, cudaFuncAttributeMaxDynamicSharedMemorySize, MG_SMEM_BYTES);
        cudaFuncSetAttribute(mma_gemm_kernel<2>, cudaFuncAttributeMaxDynamicSharedMemorySize, MG_SMEM_BYTES);
        cudaFuncSetAttribute(mma_gemm_kernel<3>, cudaFuncAttributeMaxDynamicSharedMemorySize, MG_SMEM_BYTES);
        cudaFuncSetAttribute(mma_gemm_kernel<4>, cudaFuncAttributeMaxDynamicSharedMemorySize, MG_SMEM_BYTES);
        cudaFuncSetAttribute(mma_gemm_kernel<5>, cudaFuncAttributeMaxDynamicSharedMemorySize, MG_SMEM_BYTES);
        attr_done = true;
    }

    const int MROWS = (N_NODES + 127) / 128;  // 157

    // [0] G = scale*WqWk^T (+ bvec)
    gmat_kernel<<<(131072 + 1024 + 255) / 256, 256>>>(Wq, Wk, bq);
    // [1] pack fp16 weights + biases (bvec folded into qeff bias) + x
    prep_all<<<(PREP_TOTAL + 255) / 256, 256>>>(Wv, Wskip, W1, W2, Win, bv, bskip, x);
    // [2] input projection + LN1(layer0) fused (K=64, 1 chunk)
    mma_gemm_kernel<3><<<dim3(1, MROWS), 256, MG_SMEM_BYTES>>>(
        xh, wh + W_WIN_OFF, b_in, h, nullptr,
        ah, nullptr, ln1_s, ln1_b, nullptr, N_NODES, 128, 64);
    // [3] layer-0 qeff+skip GEMM  (ncu capture slot)
    mma_gemm_kernel<4><<<dim3(5, MROWS), 256, MG_SMEM_BYTES>>>(
        ah, wh, bkvs, nullptr, nullptr,
        kvh, nullptr, nullptr, nullptr, xr, N_NODES, KVS_N, 128);
    // CSR build
    zero_cnt_kernel<<<(N_NODES + 255) / 256, 256>>>();
    deg_kernel<<<(N_EDGES + 255) / 256, 256>>>(ei);
    scan_kernel<<<1, 1024>>>();
    scatter_kernel<<<(N_EDGES + 255) / 256, 256>>>(ei);

    for (int l = 0; l < 2; l++) {
        const int wb = l * W_PER_LAYER;
        if (l == 1) {
            mma_gemm_kernel<4><<<dim3(5, MROWS), 256, MG_SMEM_BYTES>>>(
                ah, wh + wb, bkvs + l * KVS_N, nullptr, nullptr,
                kvh, nullptr, nullptr, nullptr, xr, N_NODES, KVS_N, 128);
        }
        // attention: u_h accumulation (bias folded into qeff)
        attn_u_kernel<<<(N_NODES + 3) / 4, 128>>>();
        // v-apply GEMM + beta gate + residual + LN2 -> ah
        mma_gemm_kernel<5><<<dim3(1, MROWS), 256, MG_SMEM_BYTES>>>(
            mh, wh + wb + WL_VAPP, vb + l * 128, h, g1 + l,
            ah, (float*)(Wbeta + l * 384), ln2_s + l * 128, ln2_b + l * 128, xr,
            N_NODES, 128, 512);
        // FFN1 (gelu -> fp16 mid)
        mma_gemm_kernel<1><<<dim3(4, MROWS), 256, MG_SMEM_BYTES>>>(
            ah, wh + wb + WL_W1, b1 + l * 512, nullptr, nullptr,
            mh, nullptr, nullptr, nullptr, nullptr, N_NODES, 512, 128);
        // FFN2 + residual + LN (next layer ln1, or final lno -> d_out)
        if (l == 0) {
            mma_gemm_kernel<2><<<dim3(1, MROWS), 256, MG_SMEM_BYTES>>>(
                mh, wh + wb + WL_W2, b2 + l * 128, h, g2 + l,
                ah, nullptr, ln1_s + 128, ln1_b + 128, nullptr,
                N_NODES, 128, 512);
        } else {
            mma_gemm_kernel<2><<<dim3(1, MROWS), 256, MG_SMEM_BYTES>>>(
                mh, wh + wb + WL_W2, b2 + l * 128, h, g2 + l,
                nullptr, (float*)d_out, lno_s, lno_b, nullptr,
                N_NODES, 128, 512);
        }
    }
}